// round 1
// baseline (speedup 1.0000x reference)
#include <cuda_runtime.h>
#include <math.h>

#define D_MODEL 1024
#define NUM_HEADS 16
#define HEAD_DIM 64
#define SEQ 1024
#define BATCH 2
#define ROWS (BATCH * SEQ)            // 2048
#define OUT_ELEMS   (ROWS * D_MODEL)  // 2,097,152
#define SREL_ELEMS  (BATCH * NUM_HEADS * SEQ * SEQ)  // 33,554,432

// -------- scratch (static device globals; no runtime allocation) --------
__device__ float g_Q[ROWS * D_MODEL];
__device__ float g_K[ROWS * D_MODEL];
__device__ float g_V[ROWS * D_MODEL];
__device__ float g_O[ROWS * D_MODEL];

// ============================================================
// Generic tiled SGEMM with bias: C(M,N) = A(M,K) @ B(K,N) + bias
// 128x128 block tile, BK=8, 256 threads, 8x8 per-thread (4+4 split)
// ============================================================
__global__ __launch_bounds__(256) void sgemm_bias(
    const float* __restrict__ A, const float* __restrict__ B,
    const float* __restrict__ bias, float* __restrict__ C,
    int M, int N, int K)
{
    __shared__ float As[8][128];   // [k][m]
    __shared__ float Bs[8][128];   // [k][n]

    const int tid = threadIdx.x;
    const int row0 = blockIdx.y * 128;
    const int col0 = blockIdx.x * 128;

    const int ar = tid >> 1;            // 0..127
    const int ac = (tid & 1) << 2;      // 0 or 4
    const int br = tid >> 5;            // 0..7
    const int bc = (tid & 31) << 2;     // 0..124

    const int ty = tid >> 4;            // 0..15
    const int tx = tid & 15;            // 0..15

    float acc[8][8];
    #pragma unroll
    for (int i = 0; i < 8; i++)
        #pragma unroll
        for (int j = 0; j < 8; j++) acc[i][j] = 0.f;

    for (int k0 = 0; k0 < K; k0 += 8) {
        float4 a4 = *(const float4*)(A + (size_t)(row0 + ar) * K + k0 + ac);
        As[ac + 0][ar] = a4.x;
        As[ac + 1][ar] = a4.y;
        As[ac + 2][ar] = a4.z;
        As[ac + 3][ar] = a4.w;
        float4 b4 = *(const float4*)(B + (size_t)(k0 + br) * N + col0 + bc);
        *(float4*)(&Bs[br][bc]) = b4;
        __syncthreads();

        #pragma unroll
        for (int kk = 0; kk < 8; kk++) {
            float a[8], b[8];
            *(float4*)(a)     = *(const float4*)(&As[kk][ty * 4]);
            *(float4*)(a + 4) = *(const float4*)(&As[kk][ty * 4 + 64]);
            *(float4*)(b)     = *(const float4*)(&Bs[kk][tx * 4]);
            *(float4*)(b + 4) = *(const float4*)(&Bs[kk][tx * 4 + 64]);
            #pragma unroll
            for (int i = 0; i < 8; i++)
                #pragma unroll
                for (int j = 0; j < 8; j++)
                    acc[i][j] += a[i] * b[j];
        }
        __syncthreads();
    }

    #pragma unroll
    for (int i = 0; i < 8; i++) {
        int r = row0 + ((i < 4) ? (ty * 4 + i) : (64 + ty * 4 + (i - 4)));
        #pragma unroll
        for (int j = 0; j < 8; j++) {
            int c = col0 + ((j < 4) ? (tx * 4 + j) : (64 + tx * 4 + (j - 4)));
            C[(size_t)r * N + c] = acc[i][j] + bias[c];
        }
    }
}

// ============================================================
// qe[b,h,i,k] = (k >= 1023 - i) ? dot(Qh[b,h,i,:], e_r[k,:]) : 0
// per (b,h): 1024x1024x64 GEMM. 64x64 tiles, 256 threads, 4x4/thread.
// ============================================================
__global__ __launch_bounds__(256) void qe_kernel(
    const float* __restrict__ er, float* __restrict__ qe_out)
{
    __shared__ float Qs[64][65];   // [d][i]
    __shared__ float Es[64][65];   // [d][k]

    const int tid = threadIdx.x;
    const int k0 = blockIdx.x * 64;
    const int i0 = blockIdx.y * 64;
    const int bh = blockIdx.z;
    const int b = bh >> 4, h = bh & 15;

    const float* Qbase = g_Q + (size_t)(b * SEQ) * D_MODEL + h * HEAD_DIM;

    for (int idx = tid; idx < 4096; idx += 256) {
        int r = idx >> 6, d = idx & 63;
        Qs[d][r] = Qbase[(size_t)(i0 + r) * D_MODEL + d];
        Es[d][r] = er[(size_t)(k0 + r) * HEAD_DIM + d];
    }
    __syncthreads();

    const int ty = tid >> 4, tx = tid & 15;
    const int rm = ty << 2, cn = tx << 2;

    float acc[4][4];
    #pragma unroll
    for (int u = 0; u < 4; u++)
        #pragma unroll
        for (int v = 0; v < 4; v++) acc[u][v] = 0.f;

    #pragma unroll
    for (int d = 0; d < 64; d++) {
        float a[4], e[4];
        #pragma unroll
        for (int u = 0; u < 4; u++) a[u] = Qs[d][rm + u];
        #pragma unroll
        for (int v = 0; v < 4; v++) e[v] = Es[d][cn + v];
        #pragma unroll
        for (int u = 0; u < 4; u++)
            #pragma unroll
            for (int v = 0; v < 4; v++) acc[u][v] += a[u] * e[v];
    }

    float* outp = qe_out + ((size_t)bh << 20);
    #pragma unroll
    for (int u = 0; u < 4; u++) {
        int i = i0 + rm + u;
        #pragma unroll
        for (int v = 0; v < 4; v++) {
            int k = k0 + cn + v;
            outp[((size_t)i << 10) + k] = (k >= 1023 - i) ? acc[u][v] : 0.f;
        }
    }
}

// ============================================================
// S_rel[bh,i,j] = (j <= i) ? qe[bh,i, 1023 - i + j] : 0   (shifted row copy)
// ============================================================
__global__ __launch_bounds__(256) void srel_kernel(
    const float* __restrict__ qe, float* __restrict__ srel)
{
    int idx = blockIdx.x * 256 + threadIdx.x;
    int j = idx & 1023;
    int i = (idx >> 10) & 1023;
    srel[idx] = (j <= i) ? qe[idx + (1023 - i)] : 0.f;
}

// ============================================================
// Flash-style causal attention with relative-position term.
// One block = 64 query rows of one (b,h). 256 threads, 4x4 tiles.
// O[b,s, h*64+d] written to g_O in (b,s,d_model) layout.
// ============================================================
#define ATTN_SMEM_FLOATS (4 * 64 * 65 + 3 * 64)
__global__ __launch_bounds__(256) void attn_kernel(const float* __restrict__ qe)
{
    extern __shared__ float sm[];
    float* Qs   = sm;                 // [d][i] stride 65
    float* Ks   = Qs + 64 * 65;       // [d][j] stride 65
    float* Vs   = Ks + 64 * 65;       // [j][d] stride 65
    float* Ps   = Vs + 64 * 65;       // [j][i] stride 65
    float* rowm = Ps + 64 * 65;
    float* rowl = rowm + 64;
    float* rowa = rowl + 64;

    const int tid = threadIdx.x;
    const int itile = blockIdx.x;
    const int i0 = itile * 64;
    const int bh = blockIdx.y;
    const int b = bh >> 4, h = bh & 15;

    const float* Qb = g_Q + (size_t)(b * SEQ) * D_MODEL + h * HEAD_DIM;
    const float* Kb = g_K + (size_t)(b * SEQ) * D_MODEL + h * HEAD_DIM;
    const float* Vb = g_V + (size_t)(b * SEQ) * D_MODEL + h * HEAD_DIM;
    const float* qer = qe + ((size_t)bh << 20);

    for (int idx = tid; idx < 4096; idx += 256) {
        int r = idx >> 6, d = idx & 63;
        Qs[d * 65 + r] = Qb[(size_t)(i0 + r) * D_MODEL + d];
    }
    if (tid < 64) { rowm[tid] = -1e30f; rowl[tid] = 0.f; }

    const int ty = tid >> 4, tx = tid & 15;
    const int rm = ty << 2, cn = tx << 2;

    float o[4][4];
    #pragma unroll
    for (int u = 0; u < 4; u++)
        #pragma unroll
        for (int v = 0; v < 4; v++) o[u][v] = 0.f;
    __syncthreads();

    for (int t = 0; t <= itile; t++) {
        const int j0 = t * 64;
        for (int idx = tid; idx < 4096; idx += 256) {
            int r = idx >> 6, d = idx & 63;
            Ks[d * 65 + r] = Kb[(size_t)(j0 + r) * D_MODEL + d];
            Vs[r * 65 + d] = Vb[(size_t)(j0 + r) * D_MODEL + d];
        }
        __syncthreads();

        // S tile = Q @ K^T
        float s[4][4];
        #pragma unroll
        for (int u = 0; u < 4; u++)
            #pragma unroll
            for (int v = 0; v < 4; v++) s[u][v] = 0.f;
        #pragma unroll
        for (int d = 0; d < 64; d++) {
            float a[4], kk[4];
            #pragma unroll
            for (int u = 0; u < 4; u++) a[u] = Qs[d * 65 + rm + u];
            #pragma unroll
            for (int v = 0; v < 4; v++) kk[v] = Ks[d * 65 + cn + v];
            #pragma unroll
            for (int u = 0; u < 4; u++)
                #pragma unroll
                for (int v = 0; v < 4; v++) s[u][v] += a[u] * kk[v];
        }

        // scale + rel term + causal mask; store transposed [j][i]
        #pragma unroll
        for (int u = 0; u < 4; u++) {
            int i = i0 + rm + u;
            #pragma unroll
            for (int v = 0; v < 4; v++) {
                int j = j0 + cn + v;
                float val;
                if (j <= i)
                    val = s[u][v] * 0.125f + qer[((size_t)i << 10) + (1023 - i + j)];
                else
                    val = -1e30f;
                Ps[(cn + v) * 65 + (rm + u)] = val;
            }
        }
        __syncthreads();

        // per-row online softmax stats (64 threads, one per row)
        if (tid < 64) {
            const int i = tid;
            float m_old = rowm[i];
            float m = m_old;
            for (int j = 0; j < 64; j++) m = fmaxf(m, Ps[j * 65 + i]);
            float alpha = expf(m_old - m);
            float l = rowl[i] * alpha;
            for (int j = 0; j < 64; j++) {
                float p = expf(Ps[j * 65 + i] - m);
                Ps[j * 65 + i] = p;
                l += p;
            }
            rowm[i] = m; rowl[i] = l; rowa[i] = alpha;
        }
        __syncthreads();

        // O = alpha * O + P @ V
        float al[4];
        #pragma unroll
        for (int u = 0; u < 4; u++) al[u] = rowa[rm + u];
        #pragma unroll
        for (int u = 0; u < 4; u++)
            #pragma unroll
            for (int v = 0; v < 4; v++) o[u][v] *= al[u];
        #pragma unroll
        for (int j = 0; j < 64; j++) {
            float p[4], vv[4];
            #pragma unroll
            for (int u = 0; u < 4; u++) p[u] = Ps[j * 65 + rm + u];
            #pragma unroll
            for (int v = 0; v < 4; v++) vv[v] = Vs[j * 65 + cn + v];
            #pragma unroll
            for (int u = 0; u < 4; u++)
                #pragma unroll
                for (int v = 0; v < 4; v++) o[u][v] += p[u] * vv[v];
        }
        __syncthreads();
    }

    float* Ob = g_O + (size_t)(b * SEQ) * D_MODEL + h * HEAD_DIM;
    #pragma unroll
    for (int u = 0; u < 4; u++) {
        float inv = 1.f / rowl[rm + u];
        #pragma unroll
        for (int v = 0; v < 4; v++)
            Ob[(size_t)(i0 + rm + u) * D_MODEL + (cn + v)] = o[u][v] * inv;
    }
}

// ============================================================
// Launcher
// ============================================================
extern "C" void kernel_launch(void* const* d_in, const int* in_sizes, int n_in,
                              void* d_out, int out_size)
{
    (void)in_sizes; (void)n_in; (void)out_size;
    const float* q  = (const float*)d_in[0];
    const float* k  = (const float*)d_in[1];
    const float* v  = (const float*)d_in[2];
    // d_in[3] = mask (always causal tril) — unused
    const float* Wq = (const float*)d_in[4];
    const float* bq = (const float*)d_in[5];
    const float* Wk = (const float*)d_in[6];
    const float* bk = (const float*)d_in[7];
    const float* Wv = (const float*)d_in[8];
    const float* bv = (const float*)d_in[9];
    const float* Wo = (const float*)d_in[10];
    const float* bo = (const float*)d_in[11];
    const float* er = (const float*)d_in[12];

    float* out  = (float*)d_out;             // (B,S,D)          2,097,152
    float* srel = out + OUT_ELEMS;           // (B,H,S,S)       33,554,432
    float* qe   = srel + SREL_ELEMS;         // (B,H,S,S)       33,554,432

    float *Qb, *Kb, *Vb, *Ob;
    cudaGetSymbolAddress((void**)&Qb, g_Q);
    cudaGetSymbolAddress((void**)&Kb, g_K);
    cudaGetSymbolAddress((void**)&Vb, g_V);
    cudaGetSymbolAddress((void**)&Ob, g_O);

    dim3 gproj(D_MODEL / 128, ROWS / 128);   // (8, 16)

    sgemm_bias<<<gproj, 256>>>(q, Wq, bq, Qb, ROWS, D_MODEL, D_MODEL);
    sgemm_bias<<<gproj, 256>>>(k, Wk, bk, Kb, ROWS, D_MODEL, D_MODEL);
    sgemm_bias<<<gproj, 256>>>(v, Wv, bv, Vb, ROWS, D_MODEL, D_MODEL);

    qe_kernel<<<dim3(16, 16, BATCH * NUM_HEADS), 256>>>(er, qe);

    srel_kernel<<<SREL_ELEMS / 256, 256>>>(qe, srel);

    const int attn_smem = ATTN_SMEM_FLOATS * (int)sizeof(float);
    cudaFuncSetAttribute(attn_kernel,
                         cudaFuncAttributeMaxDynamicSharedMemorySize, attn_smem);
    attn_kernel<<<dim3(16, BATCH * NUM_HEADS), 256, attn_smem>>>(qe);

    sgemm_bias<<<gproj, 256>>>(Ob, Wo, bo, out, ROWS, D_MODEL, D_MODEL);
}

// round 2
// speedup vs baseline: 1.4363x; 1.4363x over previous
#include <cuda_runtime.h>
#include <math.h>

#define D_MODEL 1024
#define NUM_HEADS 16
#define HEAD_DIM 64
#define SEQ 1024
#define BATCH 2
#define ROWS (BATCH * SEQ)            // 2048
#define OUT_ELEMS   (ROWS * D_MODEL)  // 2,097,152
#define SREL_ELEMS  (BATCH * NUM_HEADS * SEQ * SEQ)  // 33,554,432

typedef unsigned long long ull;

// ---- packed f32x2 helpers (FFMA2: 2x fp32 FMA throughput on sm_103a) ----
__device__ __forceinline__ ull pk2(float x, float y) {
    ull r; asm("mov.b64 %0,{%1,%2};" : "=l"(r) : "f"(x), "f"(y)); return r;
}
__device__ __forceinline__ void upk2(ull v, float& x, float& y) {
    asm("mov.b64 {%0,%1},%2;" : "=f"(x), "=f"(y) : "l"(v));
}
__device__ __forceinline__ void ffma2(ull& d, ull a, ull b) {
    asm("fma.rn.f32x2 %0,%1,%2,%0;" : "+l"(d) : "l"(a), "l"(b));
}
__device__ __forceinline__ ull mul2(ull a, ull b) {
    ull d; asm("mul.rn.f32x2 %0,%1,%2;" : "=l"(d) : "l"(a), "l"(b)); return d;
}

// -------- scratch (static device globals; no runtime allocation) --------
__device__ float g_Q[ROWS * D_MODEL];
__device__ float g_K[ROWS * D_MODEL];
__device__ float g_V[ROWS * D_MODEL];
__device__ float g_O[ROWS * D_MODEL];

// ============================================================
// SGEMM + bias, 128x128 tile, BK=8, 256 thr, 8x8/thread, f32x2,
// register double-buffered gmem prefetch.
// ============================================================
__global__ __launch_bounds__(256) void sgemm_bias(
    const float* __restrict__ A, const float* __restrict__ B,
    const float* __restrict__ bias, float* __restrict__ C,
    int M, int N, int K)
{
    __shared__ float As[8][128];   // [k][m]
    __shared__ float Bs[8][128];   // [k][n]

    const int tid = threadIdx.x;
    const int row0 = blockIdx.y * 128;
    const int col0 = blockIdx.x * 128;

    const int ar = tid >> 1;            // 0..127
    const int ac = (tid & 1) << 2;      // 0 or 4
    const int br = tid >> 5;            // 0..7
    const int bc = (tid & 31) << 2;     // 0..124

    const int ty = tid >> 4;            // 0..15
    const int tx = tid & 15;            // 0..15

    const float* Abase = A + (size_t)(row0 + ar) * K + ac;
    const float* Bbase = B + (size_t)br * N + col0 + bc;

    float4 a_nxt = *(const float4*)(Abase);
    float4 b_nxt = *(const float4*)(Bbase);

    ull acc2[8][4];
    #pragma unroll
    for (int i = 0; i < 8; i++)
        #pragma unroll
        for (int p = 0; p < 4; p++) acc2[i][p] = 0ull;

    for (int k0 = 0; k0 < K; k0 += 8) {
        As[ac + 0][ar] = a_nxt.x;
        As[ac + 1][ar] = a_nxt.y;
        As[ac + 2][ar] = a_nxt.z;
        As[ac + 3][ar] = a_nxt.w;
        *(float4*)(&Bs[br][bc]) = b_nxt;
        __syncthreads();

        if (k0 + 8 < K) {
            a_nxt = *(const float4*)(Abase + k0 + 8);
            b_nxt = *(const float4*)(Bbase + (size_t)(k0 + 8) * N);
        }

        #pragma unroll
        for (int kk = 0; kk < 8; kk++) {
            float a[8], b[8];
            *(float4*)(a)     = *(const float4*)(&As[kk][ty * 4]);
            *(float4*)(a + 4) = *(const float4*)(&As[kk][ty * 4 + 64]);
            *(float4*)(b)     = *(const float4*)(&Bs[kk][tx * 4]);
            *(float4*)(b + 4) = *(const float4*)(&Bs[kk][tx * 4 + 64]);
            ull b2[4];
            #pragma unroll
            for (int p = 0; p < 4; p++) b2[p] = pk2(b[2 * p], b[2 * p + 1]);
            #pragma unroll
            for (int i = 0; i < 8; i++) {
                ull aa = pk2(a[i], a[i]);
                #pragma unroll
                for (int p = 0; p < 4; p++) ffma2(acc2[i][p], aa, b2[p]);
            }
        }
        __syncthreads();
    }

    const float4 bb0 = *(const float4*)(bias + col0 + tx * 4);
    const float4 bb1 = *(const float4*)(bias + col0 + 64 + tx * 4);
    #pragma unroll
    for (int i = 0; i < 8; i++) {
        int r = row0 + ((i < 4) ? (ty * 4 + i) : (64 + ty * 4 + (i - 4)));
        float4 w0, w1;
        upk2(acc2[i][0], w0.x, w0.y); upk2(acc2[i][1], w0.z, w0.w);
        upk2(acc2[i][2], w1.x, w1.y); upk2(acc2[i][3], w1.z, w1.w);
        w0.x += bb0.x; w0.y += bb0.y; w0.z += bb0.z; w0.w += bb0.w;
        w1.x += bb1.x; w1.y += bb1.y; w1.z += bb1.z; w1.w += bb1.w;
        *(float4*)(C + (size_t)r * N + col0 + tx * 4) = w0;
        *(float4*)(C + (size_t)r * N + col0 + 64 + tx * 4) = w1;
    }
}

// ============================================================
// qe banded tiles only: 128(i) x 64(k) per block, 256 thr, 8x4/thread.
// Tile (a,c) computed iff 2a+c >= 14 (72 of 128 tiles per bh).
// ============================================================
__global__ __launch_bounds__(256) void qe_banded(
    const float* __restrict__ er, float* __restrict__ qe_out)
{
    extern __shared__ float sm[];
    float* Qs = sm;                  // [d][i], stride 129, 64x128
    float* Es = sm + 64 * 129;       // [d][k], stride 65, 64x64

    int t = blockIdx.x;              // 0..71
    int a = 0;
    while (t >= 2 * a + 2) { t -= 2 * a + 2; a++; }
    const int c = 14 - 2 * a + t;
    const int i0 = a * 128, k0 = c * 64;
    const int bh = blockIdx.y;
    const int b = bh >> 4, h = bh & 15;
    const int tid = threadIdx.x;

    const float* Qbase = g_Q + (size_t)(b * SEQ) * D_MODEL + h * HEAD_DIM;

    for (int idx = tid; idx < 2048; idx += 256) {
        int r = idx >> 4, d4 = (idx & 15) << 2;
        float4 v = *(const float4*)(Qbase + (size_t)(i0 + r) * D_MODEL + d4);
        Qs[(d4 + 0) * 129 + r] = v.x;
        Qs[(d4 + 1) * 129 + r] = v.y;
        Qs[(d4 + 2) * 129 + r] = v.z;
        Qs[(d4 + 3) * 129 + r] = v.w;
    }
    for (int idx = tid; idx < 1024; idx += 256) {
        int r = idx >> 4, d4 = (idx & 15) << 2;
        float4 v = *(const float4*)(er + (size_t)(k0 + r) * HEAD_DIM + d4);
        Es[(d4 + 0) * 65 + r] = v.x;
        Es[(d4 + 1) * 65 + r] = v.y;
        Es[(d4 + 2) * 65 + r] = v.z;
        Es[(d4 + 3) * 65 + r] = v.w;
    }
    __syncthreads();

    const int ty = tid >> 4, tx = tid & 15;
    const int rm = ty * 8, cn = tx * 4;

    ull acc2[8][2];
    #pragma unroll
    for (int u = 0; u < 8; u++) { acc2[u][0] = 0ull; acc2[u][1] = 0ull; }

    #pragma unroll 4
    for (int d = 0; d < 64; d++) {
        float e0 = Es[d * 65 + cn];
        float e1 = Es[d * 65 + cn + 1];
        float e2 = Es[d * 65 + cn + 2];
        float e3 = Es[d * 65 + cn + 3];
        ull ee0 = pk2(e0, e1), ee1 = pk2(e2, e3);
        #pragma unroll
        for (int u = 0; u < 8; u++) {
            float av = Qs[d * 129 + rm + u];
            ull aa = pk2(av, av);
            ffma2(acc2[u][0], aa, ee0);
            ffma2(acc2[u][1], aa, ee1);
        }
    }

    float* outp = qe_out + ((size_t)bh << 20);
    #pragma unroll
    for (int u = 0; u < 8; u++) {
        int i = i0 + rm + u;
        int kb = 1023 - i;
        float4 w;
        upk2(acc2[u][0], w.x, w.y);
        upk2(acc2[u][1], w.z, w.w);
        int k = k0 + cn;
        if (k + 0 < kb) w.x = 0.f;
        if (k + 1 < kb) w.y = 0.f;
        if (k + 2 < kb) w.z = 0.f;
        if (k + 3 < kb) w.w = 0.f;
        *(float4*)(outp + ((size_t)i << 10) + k) = w;
    }
}

// zero-fill the 56 all-zero tiles per bh
__global__ __launch_bounds__(256) void qe_zero(float* __restrict__ qe_out)
{
    int t = blockIdx.x;              // 0..55
    int a = 0;
    while (t >= 14 - 2 * a) { t -= 14 - 2 * a; a++; }
    const int i0 = a * 128, k0 = t * 64;
    const int bh = blockIdx.y;
    float* outp = qe_out + ((size_t)bh << 20);
    const float4 z = make_float4(0.f, 0.f, 0.f, 0.f);
    for (int idx = threadIdx.x; idx < 2048; idx += 256) {
        int r = idx >> 4, k4 = (idx & 15) << 2;
        *(float4*)(outp + ((size_t)(i0 + r) << 10) + k0 + k4) = z;
    }
}

// ============================================================
// S_rel[bh,i,j] = (j <= i) ? qe[bh,i, 1023 - i + j] : 0
// ============================================================
__global__ __launch_bounds__(256) void srel_kernel(
    const float* __restrict__ qe, float* __restrict__ srel)
{
    int idx = blockIdx.x * 256 + threadIdx.x;
    int j = idx & 1023;
    int i = (idx >> 10) & 1023;
    srel[idx] = (j <= i) ? qe[idx + (1023 - i)] : 0.f;
}

// ============================================================
// Flash-style causal attention + rel term (read from srel, contiguous).
// 64 query rows per block, 256 thr, 4x4/thread, f32x2, parallel softmax,
// register-prefetched K/V tiles. Heavy diagonal tiles scheduled first.
// ============================================================
#define ATTN_SMEM_FLOATS (4 * 64 * 65 + 3 * 64 + 2 * 256)
__global__ __launch_bounds__(256) void attn_kernel(const float* __restrict__ srel)
{
    extern __shared__ float sm[];
    float* Qs   = sm;                  // [d][i] stride 65
    float* Ks   = Qs + 64 * 65;        // [d][j] stride 65
    float* Vs   = Ks + 64 * 65;        // [j][d] stride 65
    float* Ps   = Vs + 64 * 65;        // [j][i] stride 65
    float* rowm = Ps + 64 * 65;
    float* rowl = rowm + 64;
    float* rowa = rowl + 64;
    float* pm   = rowa + 64;           // [4][64]
    float* pl   = pm + 256;            // [4][64]

    const int tid = threadIdx.x;
    const int itile = 15 - blockIdx.x;     // heavy blocks first
    const int i0 = itile * 64;
    const int bh = blockIdx.y;
    const int b = bh >> 4, h = bh & 15;

    const float* Qb = g_Q + (size_t)(b * SEQ) * D_MODEL + h * HEAD_DIM;
    const float* Kb = g_K + (size_t)(b * SEQ) * D_MODEL + h * HEAD_DIM;
    const float* Vb = g_V + (size_t)(b * SEQ) * D_MODEL + h * HEAD_DIM;
    const float* srp = srel + ((size_t)bh << 20);

    // Q tile load (scatter to [d][i], stride 65)
    for (int idx = tid; idx < 1024; idx += 256) {
        int r = idx >> 4, d4 = (idx & 15) << 2;
        float4 v = *(const float4*)(Qb + (size_t)(i0 + r) * D_MODEL + d4);
        Qs[(d4 + 0) * 65 + r] = v.x;
        Qs[(d4 + 1) * 65 + r] = v.y;
        Qs[(d4 + 2) * 65 + r] = v.z;
        Qs[(d4 + 3) * 65 + r] = v.w;
    }
    if (tid < 64) { rowm[tid] = -1e30f; rowl[tid] = 0.f; }

    const int ty = tid >> 4, tx = tid & 15;
    const int rm = ty << 2, cn = tx << 2;

    ull o2[4][2];
    #pragma unroll
    for (int u = 0; u < 4; u++) { o2[u][0] = 0ull; o2[u][1] = 0ull; }

    // prefetch K/V tile 0 into registers
    const int pr = tid >> 4;           // shared by the 4 chunks below
    float4 kn[4], vn[4];
    {
        #pragma unroll
        for (int q = 0; q < 4; q++) {
            int idx = tid + q * 256;
            int r = idx >> 4, d4 = (idx & 15) << 2;
            kn[q] = *(const float4*)(Kb + (size_t)r * D_MODEL + d4);
            vn[q] = *(const float4*)(Vb + (size_t)r * D_MODEL + d4);
        }
    }
    (void)pr;

    for (int t = 0; t <= itile; t++) {
        const int j0 = t * 64;
        // commit prefetched K/V to smem
        #pragma unroll
        for (int q = 0; q < 4; q++) {
            int idx = tid + q * 256;
            int r = idx >> 4, d4 = (idx & 15) << 2;
            Ks[(d4 + 0) * 65 + r] = kn[q].x;
            Ks[(d4 + 1) * 65 + r] = kn[q].y;
            Ks[(d4 + 2) * 65 + r] = kn[q].z;
            Ks[(d4 + 3) * 65 + r] = kn[q].w;
            *&Vs[r * 65 + d4 + 0] = vn[q].x;
            *&Vs[r * 65 + d4 + 1] = vn[q].y;
            *&Vs[r * 65 + d4 + 2] = vn[q].z;
            *&Vs[r * 65 + d4 + 3] = vn[q].w;
        }
        __syncthreads();

        if (t < itile) {
            const int j0n = j0 + 64;
            #pragma unroll
            for (int q = 0; q < 4; q++) {
                int idx = tid + q * 256;
                int r = idx >> 4, d4 = (idx & 15) << 2;
                kn[q] = *(const float4*)(Kb + (size_t)(j0n + r) * D_MODEL + d4);
                vn[q] = *(const float4*)(Vb + (size_t)(j0n + r) * D_MODEL + d4);
            }
        }

        // ---- S = Q @ K^T (f32x2) ----
        ull s2[4][2];
        #pragma unroll
        for (int u = 0; u < 4; u++) { s2[u][0] = 0ull; s2[u][1] = 0ull; }
        #pragma unroll 4
        for (int d = 0; d < 64; d++) {
            float kv0 = Ks[d * 65 + cn];
            float kv1 = Ks[d * 65 + cn + 1];
            float kv2 = Ks[d * 65 + cn + 2];
            float kv3 = Ks[d * 65 + cn + 3];
            ull kk0 = pk2(kv0, kv1), kk1 = pk2(kv2, kv3);
            #pragma unroll
            for (int u = 0; u < 4; u++) {
                float av = Qs[d * 65 + rm + u];
                ull aa = pk2(av, av);
                ffma2(s2[u][0], aa, kk0);
                ffma2(s2[u][1], aa, kk1);
            }
        }

        // scale + rel (contiguous read from srel) + causal mask → Ps [j][i]
        #pragma unroll
        for (int u = 0; u < 4; u++) {
            int i = i0 + rm + u;
            float sv[4];
            upk2(s2[u][0], sv[0], sv[1]);
            upk2(s2[u][1], sv[2], sv[3]);
            float4 rel = *(const float4*)(srp + ((size_t)i << 10) + j0 + cn);
            float rl[4] = {rel.x, rel.y, rel.z, rel.w};
            #pragma unroll
            for (int v = 0; v < 4; v++) {
                int j = j0 + cn + v;
                float val = (j <= i) ? (sv[v] * 0.125f + rl[v]) : -1e30f;
                Ps[(cn + v) * 65 + rm + u] = val;
            }
        }
        __syncthreads();

        // ---- parallel online softmax: 4 threads per row ----
        {
            int i = tid & 63, q = tid >> 6;
            float m = -1e30f;
            #pragma unroll
            for (int jj = 0; jj < 16; jj++)
                m = fmaxf(m, Ps[(q * 16 + jj) * 65 + i]);
            pm[q * 64 + i] = m;
        }
        __syncthreads();
        if (tid < 64) {
            float m_old = rowm[tid];
            float m = fmaxf(fmaxf(pm[tid], pm[64 + tid]),
                            fmaxf(pm[128 + tid], pm[192 + tid]));
            m = fmaxf(m, m_old);
            rowm[tid] = m;
            rowa[tid] = expf(m_old - m);
        }
        __syncthreads();
        {
            int i = tid & 63, q = tid >> 6;
            float m = rowm[i], s = 0.f;
            #pragma unroll
            for (int jj = 0; jj < 16; jj++) {
                int j = q * 16 + jj;
                float p = expf(Ps[j * 65 + i] - m);
                Ps[j * 65 + i] = p;
                s += p;
            }
            pl[q * 64 + i] = s;
        }
        __syncthreads();
        if (tid < 64) {
            rowl[tid] = rowl[tid] * rowa[tid] +
                        pl[tid] + pl[64 + tid] + pl[128 + tid] + pl[192 + tid];
        }
        __syncthreads();

        // ---- O = alpha * O + P @ V (f32x2) ----
        #pragma unroll
        for (int u = 0; u < 4; u++) {
            float al = rowa[rm + u];
            ull aa = pk2(al, al);
            o2[u][0] = mul2(o2[u][0], aa);
            o2[u][1] = mul2(o2[u][1], aa);
        }
        #pragma unroll 4
        for (int j = 0; j < 64; j++) {
            float v0 = Vs[j * 65 + cn];
            float v1 = Vs[j * 65 + cn + 1];
            float v2 = Vs[j * 65 + cn + 2];
            float v3 = Vs[j * 65 + cn + 3];
            ull vv0 = pk2(v0, v1), vv1 = pk2(v2, v3);
            #pragma unroll
            for (int u = 0; u < 4; u++) {
                float pv = Ps[j * 65 + rm + u];
                ull pp = pk2(pv, pv);
                ffma2(o2[u][0], pp, vv0);
                ffma2(o2[u][1], pp, vv1);
            }
        }
        __syncthreads();
    }

    float* Ob = g_O + (size_t)(b * SEQ) * D_MODEL + h * HEAD_DIM;
    #pragma unroll
    for (int u = 0; u < 4; u++) {
        float inv = 1.f / rowl[rm + u];
        float4 w;
        upk2(o2[u][0], w.x, w.y);
        upk2(o2[u][1], w.z, w.w);
        w.x *= inv; w.y *= inv; w.z *= inv; w.w *= inv;
        *(float4*)(Ob + (size_t)(i0 + rm + u) * D_MODEL + cn) = w;
    }
}

// ============================================================
// Launcher
// ============================================================
extern "C" void kernel_launch(void* const* d_in, const int* in_sizes, int n_in,
                              void* d_out, int out_size)
{
    (void)in_sizes; (void)n_in; (void)out_size;
    const float* q  = (const float*)d_in[0];
    const float* k  = (const float*)d_in[1];
    const float* v  = (const float*)d_in[2];
    // d_in[3] = mask (always causal tril) — unused
    const float* Wq = (const float*)d_in[4];
    const float* bq = (const float*)d_in[5];
    const float* Wk = (const float*)d_in[6];
    const float* bk = (const float*)d_in[7];
    const float* Wv = (const float*)d_in[8];
    const float* bv = (const float*)d_in[9];
    const float* Wo = (const float*)d_in[10];
    const float* bo = (const float*)d_in[11];
    const float* er = (const float*)d_in[12];

    float* out  = (float*)d_out;             // (B,S,D)
    float* srel = out + OUT_ELEMS;           // (B,H,S,S)
    float* qe   = srel + SREL_ELEMS;         // (B,H,S,S)

    float *Qb, *Kb, *Vb, *Ob;
    cudaGetSymbolAddress((void**)&Qb, g_Q);
    cudaGetSymbolAddress((void**)&Kb, g_K);
    cudaGetSymbolAddress((void**)&Vb, g_V);
    cudaGetSymbolAddress((void**)&Ob, g_O);

    dim3 gproj(D_MODEL / 128, ROWS / 128);   // (8, 16)

    sgemm_bias<<<gproj, 256>>>(q, Wq, bq, Qb, ROWS, D_MODEL, D_MODEL);
    sgemm_bias<<<gproj, 256>>>(k, Wk, bk, Kb, ROWS, D_MODEL, D_MODEL);
    sgemm_bias<<<gproj, 256>>>(v, Wv, bv, Vb, ROWS, D_MODEL, D_MODEL);

    const int qe_smem = (64 * 129 + 64 * 65) * (int)sizeof(float);
    cudaFuncSetAttribute(qe_banded,
                         cudaFuncAttributeMaxDynamicSharedMemorySize, qe_smem);
    qe_banded<<<dim3(72, BATCH * NUM_HEADS), 256, qe_smem>>>(er, qe);
    qe_zero<<<dim3(56, BATCH * NUM_HEADS), 256>>>(qe);

    srel_kernel<<<SREL_ELEMS / 256, 256>>>(qe, srel);

    const int attn_smem = ATTN_SMEM_FLOATS * (int)sizeof(float);
    cudaFuncSetAttribute(attn_kernel,
                         cudaFuncAttributeMaxDynamicSharedMemorySize, attn_smem);
    attn_kernel<<<dim3(16, BATCH * NUM_HEADS), 256, attn_smem>>>(srel);

    sgemm_bias<<<gproj, 256>>>(Ob, Wo, bo, out, ROWS, D_MODEL, D_MODEL);
}

// round 4
// speedup vs baseline: 1.8873x; 1.3139x over previous
#include <cuda_runtime.h>
#include <cuda_bf16.h>
#include <math.h>
#include <stdint.h>

#define D_MODEL 1024
#define NUM_HEADS 16
#define HEAD_DIM 64
#define SEQ 1024
#define BATCH 2
#define ROWS (BATCH * SEQ)            // 2048
#define OUT_ELEMS   (ROWS * D_MODEL)  // 2,097,152
#define SREL_ELEMS  (BATCH * NUM_HEADS * SEQ * SEQ)  // 33,554,432

typedef unsigned long long ull;

// ---- packed f32x2 helpers (qe / attn SIMT kernels) ----
__device__ __forceinline__ ull pk2(float x, float y) {
    ull r; asm("mov.b64 %0,{%1,%2};" : "=l"(r) : "f"(x), "f"(y)); return r;
}
__device__ __forceinline__ void upk2(ull v, float& x, float& y) {
    asm("mov.b64 {%0,%1},%2;" : "=f"(x), "=f"(y) : "l"(v));
}
__device__ __forceinline__ void ffma2(ull& d, ull a, ull b) {
    asm("fma.rn.f32x2 %0,%1,%2,%0;" : "+l"(d) : "l"(a), "l"(b));
}
__device__ __forceinline__ ull mul2(ull a, ull b) {
    ull d; asm("mul.rn.f32x2 %0,%1,%2;" : "=l"(d) : "l"(a), "l"(b)); return d;
}

// ---- HMMA helpers (baseline PTX, works on .target sm_103) ----
__device__ __forceinline__ uint32_t smem_u32(const void* p) {
    uint32_t a;
    asm("{ .reg .u64 t; cvta.to.shared.u64 t, %1; cvt.u32.u64 %0, t; }"
        : "=r"(a) : "l"(p));
    return a;
}
__device__ __forceinline__ void ldmat_x4(uint32_t& r0, uint32_t& r1,
                                         uint32_t& r2, uint32_t& r3, uint32_t addr) {
    asm volatile("ldmatrix.sync.aligned.m8n8.x4.shared.b16 {%0,%1,%2,%3}, [%4];"
                 : "=r"(r0), "=r"(r1), "=r"(r2), "=r"(r3) : "r"(addr));
}
__device__ __forceinline__ void ldmat_x2t(uint32_t& r0, uint32_t& r1, uint32_t addr) {
    asm volatile("ldmatrix.sync.aligned.m8n8.x2.trans.shared.b16 {%0,%1}, [%2];"
                 : "=r"(r0), "=r"(r1) : "r"(addr));
}
__device__ __forceinline__ void mma_bf16(float* c, const uint32_t* a,
                                         uint32_t b0, uint32_t b1) {
    asm volatile(
        "mma.sync.aligned.m16n8k16.row.col.f32.bf16.bf16.f32 "
        "{%0,%1,%2,%3}, {%4,%5,%6,%7}, {%8,%9}, {%0,%1,%2,%3};"
        : "+f"(c[0]), "+f"(c[1]), "+f"(c[2]), "+f"(c[3])
        : "r"(a[0]), "r"(a[1]), "r"(a[2]), "r"(a[3]), "r"(b0), "r"(b1));
}

// bf16 2-way split: x = hi + lo
__device__ __forceinline__ void split2(float x, float y, uint32_t& hi, uint32_t& lo) {
    __nv_bfloat162 h;
    h.x = __float2bfloat16(x);
    h.y = __float2bfloat16(y);
    __nv_bfloat162 l;
    l.x = __float2bfloat16(x - __bfloat162float(h.x));
    l.y = __float2bfloat16(y - __bfloat162float(h.y));
    hi = *(uint32_t*)&h;
    lo = *(uint32_t*)&l;
}

// -------- scratch --------
__device__ float g_Q[ROWS * D_MODEL];
__device__ float g_K[ROWS * D_MODEL];
__device__ float g_V[ROWS * D_MODEL];
__device__ float g_O[ROWS * D_MODEL];

// ============================================================
// HMMA GEMM + bias: C(2048,1024) = A @ B + bias, bf16 split x3 passes.
// CTA 128x128, 8 warps (warp tile 32x64), K-chunk 64.
// A smem [m][k] stride 72 (144B rows -> conflict-free ldmatrix);
// B smem [k][n] stride 136 (272B rows -> conflict-free ldmatrix.trans).
// ============================================================
#define AST 72
#define BST 136
#define HG_SMEM ((128 * AST * 2 + 64 * BST * 2) * 2)   // 71680 B

__global__ __launch_bounds__(256, 1) void sgemm_hmma(
    const float* __restrict__ A, const float* __restrict__ B,
    const float* __restrict__ bias, float* __restrict__ C)
{
    extern __shared__ __nv_bfloat16 sh[];
    __nv_bfloat16* Ah = sh;
    __nv_bfloat16* Al = Ah + 128 * AST;
    __nv_bfloat16* Bh = Al + 128 * AST;
    __nv_bfloat16* Bl = Bh + 64 * BST;

    const int tid = threadIdx.x;
    const int wid = tid >> 5;
    const int lane = tid & 31;
    const int row0 = blockIdx.y * 128;
    const int col0 = blockIdx.x * 128;
    const int mo = (wid >> 1) * 32;      // warp m offset
    const int no = (wid & 1) * 64;       // warp n offset

    float acc[2][8][4];
    #pragma unroll
    for (int mi = 0; mi < 2; mi++)
        #pragma unroll
        for (int ni = 0; ni < 8; ni++)
            #pragma unroll
            for (int e = 0; e < 4; e++) acc[mi][ni][e] = 0.f;

    const uint32_t sAh = smem_u32(Ah), sAl = smem_u32(Al);
    const uint32_t sBh = smem_u32(Bh), sBl = smem_u32(Bl);

    for (int c = 0; c < 16; c++) {
        const int k0 = c * 64;
        // ---- A chunk: 128 x 64 f32 -> bf16 hi/lo ----
        #pragma unroll
        for (int it = 0; it < 8; it++) {
            int idx = tid + it * 256;
            int r = idx >> 4, c4 = (idx & 15) << 2;
            float4 v = *(const float4*)(A + (size_t)(row0 + r) * 1024 + k0 + c4);
            uint32_t h01, l01, h23, l23;
            split2(v.x, v.y, h01, l01);
            split2(v.z, v.w, h23, l23);
            *(uint2*)(Ah + r * AST + c4) = make_uint2(h01, h23);
            *(uint2*)(Al + r * AST + c4) = make_uint2(l01, l23);
        }
        // ---- B chunk: 64 x 128 f32 -> bf16 hi/lo ([k][n], n contiguous) ----
        #pragma unroll
        for (int it = 0; it < 8; it++) {
            int idx = tid + it * 256;
            int r = idx >> 5, n4 = (idx & 31) << 2;
            float4 v = *(const float4*)(B + (size_t)(k0 + r) * 1024 + col0 + n4);
            uint32_t h01, l01, h23, l23;
            split2(v.x, v.y, h01, l01);
            split2(v.z, v.w, h23, l23);
            *(uint2*)(Bh + r * BST + n4) = make_uint2(h01, h23);
            *(uint2*)(Bl + r * BST + n4) = make_uint2(l01, l23);
        }
        __syncthreads();

        #pragma unroll
        for (int ks = 0; ks < 4; ks++) {
            // A fragments (x4 ldmatrix): rows mo+mi*16+(lane&15), k ks*16+(lane>>4)*8
            uint32_t ah[2][4], al[2][4];
            #pragma unroll
            for (int mi = 0; mi < 2; mi++) {
                uint32_t off = ((mo + mi * 16 + (lane & 15)) * AST
                                + ks * 16 + (lane >> 4) * 8) * 2;
                ldmat_x4(ah[mi][0], ah[mi][1], ah[mi][2], ah[mi][3], sAh + off);
                ldmat_x4(al[mi][0], al[mi][1], al[mi][2], al[mi][3], sAl + off);
            }
            // B fragments per 8-col block + 3-pass mma
            #pragma unroll
            for (int ni = 0; ni < 8; ni++) {
                uint32_t offB = ((ks * 16 + (lane & 15)) * BST + no + ni * 8) * 2;
                uint32_t bh0, bh1, bl0, bl1;
                ldmat_x2t(bh0, bh1, sBh + offB);
                ldmat_x2t(bl0, bl1, sBl + offB);
                #pragma unroll
                for (int mi = 0; mi < 2; mi++) {
                    mma_bf16(acc[mi][ni], ah[mi], bh0, bh1);
                    mma_bf16(acc[mi][ni], ah[mi], bl0, bl1);
                    mma_bf16(acc[mi][ni], al[mi], bh0, bh1);
                }
            }
        }
        __syncthreads();
    }

    // ---- epilogue: fragment -> gmem (+bias), float2 stores ----
    const int g = lane >> 2, tg = lane & 3;
    #pragma unroll
    for (int mi = 0; mi < 2; mi++) {
        #pragma unroll
        for (int ni = 0; ni < 8; ni++) {
            int colb = col0 + no + ni * 8 + tg * 2;
            float2 bb = *(const float2*)(bias + colb);
            int r0 = row0 + mo + mi * 16 + g;
            float2 w0 = make_float2(acc[mi][ni][0] + bb.x, acc[mi][ni][1] + bb.y);
            float2 w1 = make_float2(acc[mi][ni][2] + bb.x, acc[mi][ni][3] + bb.y);
            *(float2*)(C + (size_t)r0 * 1024 + colb) = w0;
            *(float2*)(C + (size_t)(r0 + 8) * 1024 + colb) = w1;
        }
    }
}

// ============================================================
// qe banded tiles only: 128(i) x 64(k) per block, 256 thr, 8x4/thread.
// ============================================================
__global__ __launch_bounds__(256) void qe_banded(
    const float* __restrict__ er, float* __restrict__ qe_out)
{
    extern __shared__ float sm[];
    float* Qs = sm;                  // [d][i], stride 129
    float* Es = sm + 64 * 129;       // [d][k], stride 65

    int t = blockIdx.x;              // 0..71
    int a = 0;
    while (t >= 2 * a + 2) { t -= 2 * a + 2; a++; }
    const int c = 14 - 2 * a + t;
    const int i0 = a * 128, k0 = c * 64;
    const int bh = blockIdx.y;
    const int b = bh >> 4, h = bh & 15;
    const int tid = threadIdx.x;

    const float* Qbase = g_Q + (size_t)(b * SEQ) * D_MODEL + h * HEAD_DIM;

    for (int idx = tid; idx < 2048; idx += 256) {
        int r = idx >> 4, d4 = (idx & 15) << 2;
        float4 v = *(const float4*)(Qbase + (size_t)(i0 + r) * D_MODEL + d4);
        Qs[(d4 + 0) * 129 + r] = v.x;
        Qs[(d4 + 1) * 129 + r] = v.y;
        Qs[(d4 + 2) * 129 + r] = v.z;
        Qs[(d4 + 3) * 129 + r] = v.w;
    }
    for (int idx = tid; idx < 1024; idx += 256) {
        int r = idx >> 4, d4 = (idx & 15) << 2;
        float4 v = *(const float4*)(er + (size_t)(k0 + r) * HEAD_DIM + d4);
        Es[(d4 + 0) * 65 + r] = v.x;
        Es[(d4 + 1) * 65 + r] = v.y;
        Es[(d4 + 2) * 65 + r] = v.z;
        Es[(d4 + 3) * 65 + r] = v.w;
    }
    __syncthreads();

    const int ty = tid >> 4, tx = tid & 15;
    const int rm = ty * 8, cn = tx * 4;

    ull acc2[8][2];
    #pragma unroll
    for (int u = 0; u < 8; u++) { acc2[u][0] = 0ull; acc2[u][1] = 0ull; }

    #pragma unroll 4
    for (int d = 0; d < 64; d++) {
        float e0 = Es[d * 65 + cn];
        float e1 = Es[d * 65 + cn + 1];
        float e2 = Es[d * 65 + cn + 2];
        float e3 = Es[d * 65 + cn + 3];
        ull ee0 = pk2(e0, e1), ee1 = pk2(e2, e3);
        #pragma unroll
        for (int u = 0; u < 8; u++) {
            float av = Qs[d * 129 + rm + u];
            ull aa = pk2(av, av);
            ffma2(acc2[u][0], aa, ee0);
            ffma2(acc2[u][1], aa, ee1);
        }
    }

    float* outp = qe_out + ((size_t)bh << 20);
    #pragma unroll
    for (int u = 0; u < 8; u++) {
        int i = i0 + rm + u;
        int kb = 1023 - i;
        float4 w;
        upk2(acc2[u][0], w.x, w.y);
        upk2(acc2[u][1], w.z, w.w);
        int k = k0 + cn;
        if (k + 0 < kb) w.x = 0.f;
        if (k + 1 < kb) w.y = 0.f;
        if (k + 2 < kb) w.z = 0.f;
        if (k + 3 < kb) w.w = 0.f;
        *(float4*)(outp + ((size_t)i << 10) + k) = w;
    }
}

// zero-fill the 56 all-zero tiles per bh
__global__ __launch_bounds__(256) void qe_zero(float* __restrict__ qe_out)
{
    int t = blockIdx.x;              // 0..55
    int a = 0;
    while (t >= 14 - 2 * a) { t -= 14 - 2 * a; a++; }
    const int i0 = a * 128, k0 = t * 64;
    const int bh = blockIdx.y;
    float* outp = qe_out + ((size_t)bh << 20);
    const float4 z = make_float4(0.f, 0.f, 0.f, 0.f);
    for (int idx = threadIdx.x; idx < 2048; idx += 256) {
        int r = idx >> 4, k4 = (idx & 15) << 2;
        *(float4*)(outp + ((size_t)(i0 + r) << 10) + k0 + k4) = z;
    }
}

// ============================================================
// S_rel[bh,i,j] = (j <= i) ? qe[bh,i, 1023 - i + j] : 0
// ============================================================
__global__ __launch_bounds__(256) void srel_kernel(
    const float* __restrict__ qe, float* __restrict__ srel)
{
    int idx = blockIdx.x * 256 + threadIdx.x;
    int j = idx & 1023;
    int i = (idx >> 10) & 1023;
    srel[idx] = (j <= i) ? qe[idx + (1023 - i)] : 0.f;
}

// ============================================================
// Flash-style causal attention + rel term (read from srel).
// ============================================================
#define ATTN_SMEM_FLOATS (4 * 64 * 65 + 3 * 64 + 2 * 256)
__global__ __launch_bounds__(256) void attn_kernel(const float* __restrict__ srel)
{
    extern __shared__ float sm[];
    float* Qs   = sm;                  // [d][i] stride 65
    float* Ks   = Qs + 64 * 65;        // [d][j] stride 65
    float* Vs   = Ks + 64 * 65;        // [j][d] stride 65
    float* Ps   = Vs + 64 * 65;        // [j][i] stride 65
    float* rowm = Ps + 64 * 65;
    float* rowl = rowm + 64;
    float* rowa = rowl + 64;
    float* pm   = rowa + 64;           // [4][64]
    float* pl   = pm + 256;            // [4][64]

    const int tid = threadIdx.x;
    const int itile = 15 - blockIdx.x;
    const int i0 = itile * 64;
    const int bh = blockIdx.y;
    const int b = bh >> 4, h = bh & 15;

    const float* Qb = g_Q + (size_t)(b * SEQ) * D_MODEL + h * HEAD_DIM;
    const float* Kb = g_K + (size_t)(b * SEQ) * D_MODEL + h * HEAD_DIM;
    const float* Vb = g_V + (size_t)(b * SEQ) * D_MODEL + h * HEAD_DIM;
    const float* srp = srel + ((size_t)bh << 20);

    for (int idx = tid; idx < 1024; idx += 256) {
        int r = idx >> 4, d4 = (idx & 15) << 2;
        float4 v = *(const float4*)(Qb + (size_t)(i0 + r) * D_MODEL + d4);
        Qs[(d4 + 0) * 65 + r] = v.x;
        Qs[(d4 + 1) * 65 + r] = v.y;
        Qs[(d4 + 2) * 65 + r] = v.z;
        Qs[(d4 + 3) * 65 + r] = v.w;
    }
    if (tid < 64) { rowm[tid] = -1e30f; rowl[tid] = 0.f; }

    const int ty = tid >> 4, tx = tid & 15;
    const int rm = ty << 2, cn = tx << 2;

    ull o2[4][2];
    #pragma unroll
    for (int u = 0; u < 4; u++) { o2[u][0] = 0ull; o2[u][1] = 0ull; }

    float4 kn[4], vn[4];
    #pragma unroll
    for (int q = 0; q < 4; q++) {
        int idx = tid + q * 256;
        int r = idx >> 4, d4 = (idx & 15) << 2;
        kn[q] = *(const float4*)(Kb + (size_t)r * D_MODEL + d4);
        vn[q] = *(const float4*)(Vb + (size_t)r * D_MODEL + d4);
    }

    for (int t = 0; t <= itile; t++) {
        const int j0 = t * 64;
        #pragma unroll
        for (int q = 0; q < 4; q++) {
            int idx = tid + q * 256;
            int r = idx >> 4, d4 = (idx & 15) << 2;
            Ks[(d4 + 0) * 65 + r] = kn[q].x;
            Ks[(d4 + 1) * 65 + r] = kn[q].y;
            Ks[(d4 + 2) * 65 + r] = kn[q].z;
            Ks[(d4 + 3) * 65 + r] = kn[q].w;
            Vs[r * 65 + d4 + 0] = vn[q].x;
            Vs[r * 65 + d4 + 1] = vn[q].y;
            Vs[r * 65 + d4 + 2] = vn[q].z;
            Vs[r * 65 + d4 + 3] = vn[q].w;
        }
        __syncthreads();

        if (t < itile) {
            const int j0n = j0 + 64;
            #pragma unroll
            for (int q = 0; q < 4; q++) {
                int idx = tid + q * 256;
                int r = idx >> 4, d4 = (idx & 15) << 2;
                kn[q] = *(const float4*)(Kb + (size_t)(j0n + r) * D_MODEL + d4);
                vn[q] = *(const float4*)(Vb + (size_t)(j0n + r) * D_MODEL + d4);
            }
        }

        ull s2[4][2];
        #pragma unroll
        for (int u = 0; u < 4; u++) { s2[u][0] = 0ull; s2[u][1] = 0ull; }
        #pragma unroll 4
        for (int d = 0; d < 64; d++) {
            float kv0 = Ks[d * 65 + cn];
            float kv1 = Ks[d * 65 + cn + 1];
            float kv2 = Ks[d * 65 + cn + 2];
            float kv3 = Ks[d * 65 + cn + 3];
            ull kk0 = pk2(kv0, kv1), kk1 = pk2(kv2, kv3);
            #pragma unroll
            for (int u = 0; u < 4; u++) {
                float av = Qs[d * 65 + rm + u];
                ull aa = pk2(av, av);
                ffma2(s2[u][0], aa, kk0);
                ffma2(s2[u][1], aa, kk1);
            }
        }

        #pragma unroll
        for (int u = 0; u < 4; u++) {
            int i = i0 + rm + u;
            float sv[4];
            upk2(s2[u][0], sv[0], sv[1]);
            upk2(s2[u][1], sv[2], sv[3]);
            float4 rel = *(const float4*)(srp + ((size_t)i << 10) + j0 + cn);
            float rl[4] = {rel.x, rel.y, rel.z, rel.w};
            #pragma unroll
            for (int v = 0; v < 4; v++) {
                int j = j0 + cn + v;
                float val = (j <= i) ? (sv[v] * 0.125f + rl[v]) : -1e30f;
                Ps[(cn + v) * 65 + rm + u] = val;
            }
        }
        __syncthreads();

        {
            int i = tid & 63, q = tid >> 6;
            float m = -1e30f;
            #pragma unroll
            for (int jj = 0; jj < 16; jj++)
                m = fmaxf(m, Ps[(q * 16 + jj) * 65 + i]);
            pm[q * 64 + i] = m;
        }
        __syncthreads();
        if (tid < 64) {
            float m_old = rowm[tid];
            float m = fmaxf(fmaxf(pm[tid], pm[64 + tid]),
                            fmaxf(pm[128 + tid], pm[192 + tid]));
            m = fmaxf(m, m_old);
            rowm[tid] = m;
            rowa[tid] = expf(m_old - m);
        }
        __syncthreads();
        {
            int i = tid & 63, q = tid >> 6;
            float m = rowm[i], s = 0.f;
            #pragma unroll
            for (int jj = 0; jj < 16; jj++) {
                int j = q * 16 + jj;
                float p = expf(Ps[j * 65 + i] - m);
                Ps[j * 65 + i] = p;
                s += p;
            }
            pl[q * 64 + i] = s;
        }
        __syncthreads();
        if (tid < 64) {
            rowl[tid] = rowl[tid] * rowa[tid] +
                        pl[tid] + pl[64 + tid] + pl[128 + tid] + pl[192 + tid];
        }
        __syncthreads();

        #pragma unroll
        for (int u = 0; u < 4; u++) {
            float al = rowa[rm + u];
            ull aa = pk2(al, al);
            o2[u][0] = mul2(o2[u][0], aa);
            o2[u][1] = mul2(o2[u][1], aa);
        }
        #pragma unroll 4
        for (int j = 0; j < 64; j++) {
            float v0 = Vs[j * 65 + cn];
            float v1 = Vs[j * 65 + cn + 1];
            float v2 = Vs[j * 65 + cn + 2];
            float v3 = Vs[j * 65 + cn + 3];
            ull vv0 = pk2(v0, v1), vv1 = pk2(v2, v3);
            #pragma unroll
            for (int u = 0; u < 4; u++) {
                float pv = Ps[j * 65 + rm + u];
                ull pp = pk2(pv, pv);
                ffma2(o2[u][0], pp, vv0);
                ffma2(o2[u][1], pp, vv1);
            }
        }
        __syncthreads();
    }

    float* Ob = g_O + (size_t)(b * SEQ) * D_MODEL + h * HEAD_DIM;
    #pragma unroll
    for (int u = 0; u < 4; u++) {
        float inv = 1.f / rowl[rm + u];
        float4 w;
        upk2(o2[u][0], w.x, w.y);
        upk2(o2[u][1], w.z, w.w);
        w.x *= inv; w.y *= inv; w.z *= inv; w.w *= inv;
        *(float4*)(Ob + (size_t)(i0 + rm + u) * D_MODEL + cn) = w;
    }
}

// ============================================================
// Launcher
// ============================================================
extern "C" void kernel_launch(void* const* d_in, const int* in_sizes, int n_in,
                              void* d_out, int out_size)
{
    (void)in_sizes; (void)n_in; (void)out_size;
    const float* q  = (const float*)d_in[0];
    const float* k  = (const float*)d_in[1];
    const float* v  = (const float*)d_in[2];
    const float* Wq = (const float*)d_in[4];
    const float* bq = (const float*)d_in[5];
    const float* Wk = (const float*)d_in[6];
    const float* bk = (const float*)d_in[7];
    const float* Wv = (const float*)d_in[8];
    const float* bv = (const float*)d_in[9];
    const float* Wo = (const float*)d_in[10];
    const float* bo = (const float*)d_in[11];
    const float* er = (const float*)d_in[12];

    float* out  = (float*)d_out;             // (B,S,D)
    float* srel = out + OUT_ELEMS;           // (B,H,S,S)
    float* qe   = srel + SREL_ELEMS;         // (B,H,S,S)

    float *Qb, *Kb, *Vb, *Ob;
    cudaGetSymbolAddress((void**)&Qb, g_Q);
    cudaGetSymbolAddress((void**)&Kb, g_K);
    cudaGetSymbolAddress((void**)&Vb, g_V);
    cudaGetSymbolAddress((void**)&Ob, g_O);

    cudaFuncSetAttribute(sgemm_hmma,
                         cudaFuncAttributeMaxDynamicSharedMemorySize, HG_SMEM);

    dim3 gproj(D_MODEL / 128, ROWS / 128);   // (8, 16)

    sgemm_hmma<<<gproj, 256, HG_SMEM>>>(q, Wq, bq, Qb);
    sgemm_hmma<<<gproj, 256, HG_SMEM>>>(k, Wk, bk, Kb);
    sgemm_hmma<<<gproj, 256, HG_SMEM>>>(v, Wv, bv, Vb);

    const int qe_smem = (64 * 129 + 64 * 65) * (int)sizeof(float);
    cudaFuncSetAttribute(qe_banded,
                         cudaFuncAttributeMaxDynamicSharedMemorySize, qe_smem);
    qe_banded<<<dim3(72, BATCH * NUM_HEADS), 256, qe_smem>>>(er, qe);
    qe_zero<<<dim3(56, BATCH * NUM_HEADS), 256>>>(qe);

    srel_kernel<<<SREL_ELEMS / 256, 256>>>(qe, srel);

    const int attn_smem = ATTN_SMEM_FLOATS * (int)sizeof(float);
    cudaFuncSetAttribute(attn_kernel,
                         cudaFuncAttributeMaxDynamicSharedMemorySize, attn_smem);
    attn_kernel<<<dim3(16, BATCH * NUM_HEADS), 256, attn_smem>>>(srel);

    sgemm_hmma<<<gproj, 256, HG_SMEM>>>(Ob, Wo, bo, out);
}

// round 6
// speedup vs baseline: 2.6057x; 1.3807x over previous
#include <cuda_runtime.h>
#include <cuda_bf16.h>
#include <math.h>
#include <stdint.h>

#define D_MODEL 1024
#define NUM_HEADS 16
#define HEAD_DIM 64
#define SEQ 1024
#define BATCH 2
#define ROWS (BATCH * SEQ)            // 2048
#define OUT_ELEMS   (ROWS * D_MODEL)  // 2,097,152
#define SREL_ELEMS  (BATCH * NUM_HEADS * SEQ * SEQ)  // 33,554,432
#define L2E 1.4426950408889634f

typedef unsigned long long ull;

// ---- HMMA helpers (baseline PTX, works on .target sm_103) ----
__device__ __forceinline__ uint32_t smem_u32(const void* p) {
    uint32_t a;
    asm("{ .reg .u64 t; cvta.to.shared.u64 t, %1; cvt.u32.u64 %0, t; }"
        : "=r"(a) : "l"(p));
    return a;
}
__device__ __forceinline__ void ldmat_x4(uint32_t& r0, uint32_t& r1,
                                         uint32_t& r2, uint32_t& r3, uint32_t addr) {
    asm volatile("ldmatrix.sync.aligned.m8n8.x4.shared.b16 {%0,%1,%2,%3}, [%4];"
                 : "=r"(r0), "=r"(r1), "=r"(r2), "=r"(r3) : "r"(addr));
}
__device__ __forceinline__ void ldmat_x4t(uint32_t& r0, uint32_t& r1,
                                          uint32_t& r2, uint32_t& r3, uint32_t addr) {
    asm volatile("ldmatrix.sync.aligned.m8n8.x4.trans.shared.b16 {%0,%1,%2,%3}, [%4];"
                 : "=r"(r0), "=r"(r1), "=r"(r2), "=r"(r3) : "r"(addr));
}
__device__ __forceinline__ void ldmat_x2t(uint32_t& r0, uint32_t& r1, uint32_t addr) {
    asm volatile("ldmatrix.sync.aligned.m8n8.x2.trans.shared.b16 {%0,%1}, [%2];"
                 : "=r"(r0), "=r"(r1) : "r"(addr));
}
__device__ __forceinline__ void mma_bf16(float* c, const uint32_t* a,
                                         uint32_t b0, uint32_t b1) {
    asm volatile(
        "mma.sync.aligned.m16n8k16.row.col.f32.bf16.bf16.f32 "
        "{%0,%1,%2,%3}, {%4,%5,%6,%7}, {%8,%9}, {%0,%1,%2,%3};"
        : "+f"(c[0]), "+f"(c[1]), "+f"(c[2]), "+f"(c[3])
        : "r"(a[0]), "r"(a[1]), "r"(a[2]), "r"(a[3]), "r"(b0), "r"(b1));
}
__device__ __forceinline__ float ex2(float x) {
    float r; asm("ex2.approx.f32 %0,%1;" : "=f"(r) : "f"(x)); return r;
}

// bf16 2-way split: x = hi + lo
__device__ __forceinline__ void split2(float x, float y, uint32_t& hi, uint32_t& lo) {
    __nv_bfloat162 h;
    h.x = __float2bfloat16(x);
    h.y = __float2bfloat16(y);
    __nv_bfloat162 l;
    l.x = __float2bfloat16(x - __bfloat162float(h.x));
    l.y = __float2bfloat16(y - __bfloat162float(h.y));
    hi = *(uint32_t*)&h;
    lo = *(uint32_t*)&l;
}

// -------- scratch --------
__device__ float g_Q[ROWS * D_MODEL];
__device__ float g_K[ROWS * D_MODEL];
__device__ float g_V[ROWS * D_MODEL];
__device__ float g_O[ROWS * D_MODEL];

// ============================================================
// HMMA GEMM + bias (unchanged from R4 — proven)
// ============================================================
#define AST 72
#define BST 136
#define HG_SMEM ((128 * AST * 2 + 64 * BST * 2) * 2)   // 71680 B

__global__ __launch_bounds__(256, 1) void sgemm_hmma(
    const float* __restrict__ A, const float* __restrict__ B,
    const float* __restrict__ bias, float* __restrict__ C)
{
    extern __shared__ __nv_bfloat16 sh[];
    __nv_bfloat16* Ah = sh;
    __nv_bfloat16* Al = Ah + 128 * AST;
    __nv_bfloat16* Bh = Al + 128 * AST;
    __nv_bfloat16* Bl = Bh + 64 * BST;

    const int tid = threadIdx.x;
    const int wid = tid >> 5;
    const int lane = tid & 31;
    const int row0 = blockIdx.y * 128;
    const int col0 = blockIdx.x * 128;
    const int mo = (wid >> 1) * 32;
    const int no = (wid & 1) * 64;

    float acc[2][8][4];
    #pragma unroll
    for (int mi = 0; mi < 2; mi++)
        #pragma unroll
        for (int ni = 0; ni < 8; ni++)
            #pragma unroll
            for (int e = 0; e < 4; e++) acc[mi][ni][e] = 0.f;

    const uint32_t sAh = smem_u32(Ah), sAl = smem_u32(Al);
    const uint32_t sBh = smem_u32(Bh), sBl = smem_u32(Bl);

    for (int c = 0; c < 16; c++) {
        const int k0 = c * 64;
        #pragma unroll
        for (int it = 0; it < 8; it++) {
            int idx = tid + it * 256;
            int r = idx >> 4, c4 = (idx & 15) << 2;
            float4 v = *(const float4*)(A + (size_t)(row0 + r) * 1024 + k0 + c4);
            uint32_t h01, l01, h23, l23;
            split2(v.x, v.y, h01, l01);
            split2(v.z, v.w, h23, l23);
            *(uint2*)(Ah + r * AST + c4) = make_uint2(h01, h23);
            *(uint2*)(Al + r * AST + c4) = make_uint2(l01, l23);
        }
        #pragma unroll
        for (int it = 0; it < 8; it++) {
            int idx = tid + it * 256;
            int r = idx >> 5, n4 = (idx & 31) << 2;
            float4 v = *(const float4*)(B + (size_t)(k0 + r) * 1024 + col0 + n4);
            uint32_t h01, l01, h23, l23;
            split2(v.x, v.y, h01, l01);
            split2(v.z, v.w, h23, l23);
            *(uint2*)(Bh + r * BST + n4) = make_uint2(h01, h23);
            *(uint2*)(Bl + r * BST + n4) = make_uint2(l01, l23);
        }
        __syncthreads();

        #pragma unroll
        for (int ks = 0; ks < 4; ks++) {
            uint32_t ah[2][4], al[2][4];
            #pragma unroll
            for (int mi = 0; mi < 2; mi++) {
                uint32_t off = ((mo + mi * 16 + (lane & 15)) * AST
                                + ks * 16 + (lane >> 4) * 8) * 2;
                ldmat_x4(ah[mi][0], ah[mi][1], ah[mi][2], ah[mi][3], sAh + off);
                ldmat_x4(al[mi][0], al[mi][1], al[mi][2], al[mi][3], sAl + off);
            }
            #pragma unroll
            for (int ni = 0; ni < 8; ni++) {
                uint32_t offB = ((ks * 16 + (lane & 15)) * BST + no + ni * 8) * 2;
                uint32_t bh0, bh1, bl0, bl1;
                ldmat_x2t(bh0, bh1, sBh + offB);
                ldmat_x2t(bl0, bl1, sBl + offB);
                #pragma unroll
                for (int mi = 0; mi < 2; mi++) {
                    mma_bf16(acc[mi][ni], ah[mi], bh0, bh1);
                    mma_bf16(acc[mi][ni], ah[mi], bl0, bl1);
                    mma_bf16(acc[mi][ni], al[mi], bh0, bh1);
                }
            }
        }
        __syncthreads();
    }

    const int g = lane >> 2, tg = lane & 3;
    #pragma unroll
    for (int mi = 0; mi < 2; mi++) {
        #pragma unroll
        for (int ni = 0; ni < 8; ni++) {
            int colb = col0 + no + ni * 8 + tg * 2;
            float2 bb = *(const float2*)(bias + colb);
            int r0 = row0 + mo + mi * 16 + g;
            float2 w0 = make_float2(acc[mi][ni][0] + bb.x, acc[mi][ni][1] + bb.y);
            float2 w1 = make_float2(acc[mi][ni][2] + bb.x, acc[mi][ni][3] + bb.y);
            *(float2*)(C + (size_t)r0 * 1024 + colb) = w0;
            *(float2*)(C + (size_t)(r0 + 8) * 1024 + colb) = w1;
        }
    }
}

// ============================================================
// qe via HMMA, banded tiles: 128(i) x 64(k), K-dim = 64 (head dim).
// 8 warps, warp = 16 rows x 64 cols. bf16 split x3.
// ============================================================
#define KST 72
#define QE_SMEM ((2 * 128 * KST + 2 * 64 * KST) * 2)   // 55296 B

__global__ __launch_bounds__(256, 1) void qe_hmma(
    const float* __restrict__ er, float* __restrict__ qe_out)
{
    extern __shared__ __nv_bfloat16 sh[];
    __nv_bfloat16* Qh = sh;
    __nv_bfloat16* Ql = Qh + 128 * KST;
    __nv_bfloat16* Eh = Ql + 128 * KST;
    __nv_bfloat16* El = Eh + 64 * KST;

    int t = blockIdx.x;              // 0..71
    int a = 0;
    while (t >= 2 * a + 2) { t -= 2 * a + 2; a++; }
    const int c = 14 - 2 * a + t;
    const int i0 = a * 128, k0 = c * 64;
    const int bh = blockIdx.y;
    const int b = bh >> 4, h = bh & 15;
    const int tid = threadIdx.x;
    const int wid = tid >> 5;
    const int lane = tid & 31;
    const int g = lane >> 2, tg = lane & 3;
    const int mo = wid * 16;

    const float* Qg = g_Q + (size_t)(b * SEQ) * D_MODEL + h * HEAD_DIM;

    // stage Q 128x64 and E 64x64 (split)
    #pragma unroll
    for (int it = 0; it < 8; it++) {
        int idx = tid + it * 256;
        int r = idx >> 4, c4 = (idx & 15) << 2;
        float4 v = *(const float4*)(Qg + (size_t)(i0 + r) * 1024 + c4);
        uint32_t h01, l01, h23, l23;
        split2(v.x, v.y, h01, l01);
        split2(v.z, v.w, h23, l23);
        *(uint2*)(Qh + r * KST + c4) = make_uint2(h01, h23);
        *(uint2*)(Ql + r * KST + c4) = make_uint2(l01, l23);
    }
    #pragma unroll
    for (int it = 0; it < 4; it++) {
        int idx = tid + it * 256;
        int r = idx >> 4, c4 = (idx & 15) << 2;
        float4 v = *(const float4*)(er + (size_t)(k0 + r) * HEAD_DIM + c4);
        uint32_t h01, l01, h23, l23;
        split2(v.x, v.y, h01, l01);
        split2(v.z, v.w, h23, l23);
        *(uint2*)(Eh + r * KST + c4) = make_uint2(h01, h23);
        *(uint2*)(El + r * KST + c4) = make_uint2(l01, l23);
    }
    __syncthreads();

    const uint32_t sQh = smem_u32(Qh), sQl = smem_u32(Ql);
    const uint32_t sEh = smem_u32(Eh), sEl = smem_u32(El);

    // Q fragments
    uint32_t qh[4][4], ql[4][4];
    #pragma unroll
    for (int kb = 0; kb < 4; kb++) {
        uint32_t off = ((mo + (lane & 15)) * KST + kb * 16 + (lane >> 4) * 8) * 2;
        ldmat_x4(qh[kb][0], qh[kb][1], qh[kb][2], qh[kb][3], sQh + off);
        ldmat_x4(ql[kb][0], ql[kb][1], ql[kb][2], ql[kb][3], sQl + off);
    }

    float sa[8][4];
    #pragma unroll
    for (int n = 0; n < 8; n++)
        #pragma unroll
        for (int e = 0; e < 4; e++) sa[n][e] = 0.f;

    #pragma unroll
    for (int ks = 0; ks < 4; ks++) {
        uint32_t ebh[8][2], ebl[8][2];
        #pragma unroll
        for (int np = 0; np < 4; np++) {
            uint32_t off = ((np * 16 + ((lane >> 4) << 3) + (lane & 7)) * KST
                            + ks * 16 + ((lane >> 3) & 1) * 8) * 2;
            uint32_t t0, t1, t2, t3;
            ldmat_x4(t0, t1, t2, t3, sEh + off);
            ebh[2 * np][0] = t0; ebh[2 * np][1] = t1;
            ebh[2 * np + 1][0] = t2; ebh[2 * np + 1][1] = t3;
            ldmat_x4(t0, t1, t2, t3, sEl + off);
            ebl[2 * np][0] = t0; ebl[2 * np][1] = t1;
            ebl[2 * np + 1][0] = t2; ebl[2 * np + 1][1] = t3;
        }
        #pragma unroll
        for (int n = 0; n < 8; n++) {
            mma_bf16(sa[n], qh[ks], ebh[n][0], ebh[n][1]);
            mma_bf16(sa[n], qh[ks], ebl[n][0], ebl[n][1]);
            mma_bf16(sa[n], ql[ks], ebh[n][0], ebh[n][1]);
        }
    }

    // mask (k >= 1023 - i) and store
    const int r0g = i0 + mo + g;
    const int r1g = r0g + 8;
    float* outp = qe_out + ((size_t)bh << 20);
    #pragma unroll
    for (int n = 0; n < 8; n++) {
        int col = k0 + n * 8 + tg * 2;
        float2 w0, w1;
        w0.x = (col     >= 1023 - r0g) ? sa[n][0] : 0.f;
        w0.y = (col + 1 >= 1023 - r0g) ? sa[n][1] : 0.f;
        w1.x = (col     >= 1023 - r1g) ? sa[n][2] : 0.f;
        w1.y = (col + 1 >= 1023 - r1g) ? sa[n][3] : 0.f;
        *(float2*)(outp + ((size_t)r0g << 10) + col) = w0;
        *(float2*)(outp + ((size_t)r1g << 10) + col) = w1;
    }
}

// zero-fill the 56 all-zero tiles per bh
__global__ __launch_bounds__(256) void qe_zero(float* __restrict__ qe_out)
{
    int t = blockIdx.x;              // 0..55
    int a = 0;
    while (t >= 14 - 2 * a) { t -= 14 - 2 * a; a++; }
    const int i0 = a * 128, k0 = t * 64;
    const int bh = blockIdx.y;
    float* outp = qe_out + ((size_t)bh << 20);
    const float4 z = make_float4(0.f, 0.f, 0.f, 0.f);
    for (int idx = threadIdx.x; idx < 2048; idx += 256) {
        int r = idx >> 4, k4 = (idx & 15) << 2;
        *(float4*)(outp + ((size_t)(i0 + r) << 10) + k0 + k4) = z;
    }
}

// ============================================================
// S_rel[bh,i,j] = (j <= i) ? qe[bh,i, 1023 - i + j] : 0
// ============================================================
__global__ __launch_bounds__(256) void srel_kernel(
    const float* __restrict__ qe, float* __restrict__ srel)
{
    int idx = blockIdx.x * 256 + threadIdx.x;
    int j = idx & 1023;
    int i = (idx >> 10) & 1023;
    srel[idx] = (j <= i) ? qe[idx + (1023 - i)] : 0.f;
}

// ============================================================
// Flash attention via HMMA. CTA = 128 q-rows of one (b,h).
// 8 warps, warp = 16 rows x 64-col j-tile; warp-local online softmax.
// QK: bf16 split x3; PV: Ph*Vh + Ph*Vl + Pl*Vh.
// ============================================================
#define AT_SMEM ((2 * 128 * KST + 4 * 64 * KST) * 2)   // 73728 B

__global__ __launch_bounds__(256, 1) void attn_hmma(const float* __restrict__ srel)
{
    extern __shared__ __nv_bfloat16 sh[];
    __nv_bfloat16* Qh = sh;
    __nv_bfloat16* Ql = Qh + 128 * KST;
    __nv_bfloat16* Kh = Ql + 128 * KST;
    __nv_bfloat16* Kl = Kh + 64 * KST;
    __nv_bfloat16* Vh = Kl + 64 * KST;
    __nv_bfloat16* Vl = Vh + 64 * KST;

    const int tid = threadIdx.x;
    const int wid = tid >> 5;
    const int lane = tid & 31;
    const int g = lane >> 2, tg = lane & 3;
    const int a = 7 - blockIdx.x;          // heavy CTAs first
    const int i0 = a * 128;
    const int bh = blockIdx.y;
    const int b = bh >> 4, h = bh & 15;
    const int mo = wid * 16;
    const int njt = 2 * a + 2;

    const float* Qg = g_Q + (size_t)(b * SEQ) * D_MODEL + h * HEAD_DIM;
    const float* Kg = g_K + (size_t)(b * SEQ) * D_MODEL + h * HEAD_DIM;
    const float* Vg = g_V + (size_t)(b * SEQ) * D_MODEL + h * HEAD_DIM;
    const float* srp = srel + ((size_t)bh << 20);

    // stage Q (split)
    #pragma unroll
    for (int it = 0; it < 8; it++) {
        int idx = tid + it * 256;
        int r = idx >> 4, c4 = (idx & 15) << 2;
        float4 v = *(const float4*)(Qg + (size_t)(i0 + r) * 1024 + c4);
        uint32_t h01, l01, h23, l23;
        split2(v.x, v.y, h01, l01);
        split2(v.z, v.w, h23, l23);
        *(uint2*)(Qh + r * KST + c4) = make_uint2(h01, h23);
        *(uint2*)(Ql + r * KST + c4) = make_uint2(l01, l23);
    }
    __syncthreads();

    const uint32_t sQh = smem_u32(Qh), sQl = smem_u32(Ql);
    const uint32_t sKh = smem_u32(Kh), sKl = smem_u32(Kl);
    const uint32_t sVh = smem_u32(Vh), sVl = smem_u32(Vl);

    uint32_t qh[4][4], ql[4][4];
    #pragma unroll
    for (int kb = 0; kb < 4; kb++) {
        uint32_t off = ((mo + (lane & 15)) * KST + kb * 16 + (lane >> 4) * 8) * 2;
        ldmat_x4(qh[kb][0], qh[kb][1], qh[kb][2], qh[kb][3], sQh + off);
        ldmat_x4(ql[kb][0], ql[kb][1], ql[kb][2], ql[kb][3], sQl + off);
    }

    float O[8][4];
    #pragma unroll
    for (int n = 0; n < 8; n++)
        #pragma unroll
        for (int e = 0; e < 4; e++) O[n][e] = 0.f;
    float m0 = -1e30f, m1 = -1e30f, l0 = 0.f, l1 = 0.f;

    const int r0g = i0 + mo + g;
    const int r1g = r0g + 8;

    for (int t = 0; t < njt; t++) {
        const int j0 = t * 64;
        __syncthreads();   // previous tile's smem reads complete
        // stage K,V tile (split)
        #pragma unroll
        for (int it = 0; it < 4; it++) {
            int idx = tid + it * 256;
            int r = idx >> 4, c4 = (idx & 15) << 2;
            float4 kv = *(const float4*)(Kg + (size_t)(j0 + r) * 1024 + c4);
            float4 vv = *(const float4*)(Vg + (size_t)(j0 + r) * 1024 + c4);
            uint32_t h01, l01, h23, l23;
            split2(kv.x, kv.y, h01, l01);
            split2(kv.z, kv.w, h23, l23);
            *(uint2*)(Kh + r * KST + c4) = make_uint2(h01, h23);
            *(uint2*)(Kl + r * KST + c4) = make_uint2(l01, l23);
            split2(vv.x, vv.y, h01, l01);
            split2(vv.z, vv.w, h23, l23);
            *(uint2*)(Vh + r * KST + c4) = make_uint2(h01, h23);
            *(uint2*)(Vl + r * KST + c4) = make_uint2(l01, l23);
        }
        __syncthreads();

        if (i0 + mo + 15 < j0) continue;   // warp fully masked for this tile

        // ---- S = Q @ K^T ----
        float sa[8][4];
        #pragma unroll
        for (int n = 0; n < 8; n++)
            #pragma unroll
            for (int e = 0; e < 4; e++) sa[n][e] = 0.f;
        #pragma unroll
        for (int ks = 0; ks < 4; ks++) {
            uint32_t kbh[8][2], kbl[8][2];
            #pragma unroll
            for (int np = 0; np < 4; np++) {
                uint32_t off = ((np * 16 + ((lane >> 4) << 3) + (lane & 7)) * KST
                                + ks * 16 + ((lane >> 3) & 1) * 8) * 2;
                uint32_t t0, t1, t2, t3;
                ldmat_x4(t0, t1, t2, t3, sKh + off);
                kbh[2 * np][0] = t0; kbh[2 * np][1] = t1;
                kbh[2 * np + 1][0] = t2; kbh[2 * np + 1][1] = t3;
                ldmat_x4(t0, t1, t2, t3, sKl + off);
                kbl[2 * np][0] = t0; kbl[2 * np][1] = t1;
                kbl[2 * np + 1][0] = t2; kbl[2 * np + 1][1] = t3;
            }
            #pragma unroll
            for (int n = 0; n < 8; n++) {
                mma_bf16(sa[n], qh[ks], kbh[n][0], kbh[n][1]);
                mma_bf16(sa[n], qh[ks], kbl[n][0], kbl[n][1]);
                mma_bf16(sa[n], ql[ks], kbh[n][0], kbh[n][1]);
            }
        }

        // ---- scale + rel + causal mask, row max ----
        float tm0 = -1e30f, tm1 = -1e30f;
        #pragma unroll
        for (int n = 0; n < 8; n++) {
            int col = j0 + n * 8 + tg * 2;
            float2 e0 = *(const float2*)(srp + ((size_t)r0g << 10) + col);
            float2 e1 = *(const float2*)(srp + ((size_t)r1g << 10) + col);
            sa[n][0] = (col     <= r0g) ? sa[n][0] * 0.125f + e0.x : -1e30f;
            sa[n][1] = (col + 1 <= r0g) ? sa[n][1] * 0.125f + e0.y : -1e30f;
            sa[n][2] = (col     <= r1g) ? sa[n][2] * 0.125f + e1.x : -1e30f;
            sa[n][3] = (col + 1 <= r1g) ? sa[n][3] * 0.125f + e1.y : -1e30f;
            tm0 = fmaxf(tm0, fmaxf(sa[n][0], sa[n][1]));
            tm1 = fmaxf(tm1, fmaxf(sa[n][2], sa[n][3]));
        }
        tm0 = fmaxf(tm0, __shfl_xor_sync(0xffffffffu, tm0, 1));
        tm0 = fmaxf(tm0, __shfl_xor_sync(0xffffffffu, tm0, 2));
        tm1 = fmaxf(tm1, __shfl_xor_sync(0xffffffffu, tm1, 1));
        tm1 = fmaxf(tm1, __shfl_xor_sync(0xffffffffu, tm1, 2));
        float nm0 = fmaxf(m0, tm0), nm1 = fmaxf(m1, tm1);
        float al0 = ex2((m0 - nm0) * L2E), al1 = ex2((m1 - nm1) * L2E);
        m0 = nm0; m1 = nm1;

        // ---- P = exp(S - m), row sums ----
        float rs0 = 0.f, rs1 = 0.f;
        #pragma unroll
        for (int n = 0; n < 8; n++) {
            sa[n][0] = ex2((sa[n][0] - nm0) * L2E);
            sa[n][1] = ex2((sa[n][1] - nm0) * L2E);
            sa[n][2] = ex2((sa[n][2] - nm1) * L2E);
            sa[n][3] = ex2((sa[n][3] - nm1) * L2E);
            rs0 += sa[n][0] + sa[n][1];
            rs1 += sa[n][2] + sa[n][3];
        }
        rs0 += __shfl_xor_sync(0xffffffffu, rs0, 1);
        rs0 += __shfl_xor_sync(0xffffffffu, rs0, 2);
        rs1 += __shfl_xor_sync(0xffffffffu, rs1, 1);
        rs1 += __shfl_xor_sync(0xffffffffu, rs1, 2);
        l0 = l0 * al0 + rs0;
        l1 = l1 * al1 + rs1;

        // rescale O
        #pragma unroll
        for (int n = 0; n < 8; n++) {
            O[n][0] *= al0; O[n][1] *= al0;
            O[n][2] *= al1; O[n][3] *= al1;
        }

        // ---- pack P fragments (hi/lo) ----
        uint32_t pa[4][4], pb[4][4];
        #pragma unroll
        for (int kb = 0; kb < 4; kb++) {
            split2(sa[2 * kb][0],     sa[2 * kb][1],     pa[kb][0], pb[kb][0]);
            split2(sa[2 * kb][2],     sa[2 * kb][3],     pa[kb][1], pb[kb][1]);
            split2(sa[2 * kb + 1][0], sa[2 * kb + 1][1], pa[kb][2], pb[kb][2]);
            split2(sa[2 * kb + 1][2], sa[2 * kb + 1][3], pa[kb][3], pb[kb][3]);
        }

        // ---- O += P @ V ----
        #pragma unroll
        for (int kb = 0; kb < 4; kb++) {
            uint32_t vbh[8][2], vbl[8][2];
            #pragma unroll
            for (int np = 0; np < 4; np++) {
                uint32_t off = ((kb * 16 + (lane & 15)) * KST
                                + np * 16 + ((lane >> 4) << 3)) * 2;
                uint32_t t0, t1, t2, t3;
                ldmat_x4t(t0, t1, t2, t3, sVh + off);
                vbh[2 * np][0] = t0; vbh[2 * np][1] = t1;
                vbh[2 * np + 1][0] = t2; vbh[2 * np + 1][1] = t3;
                ldmat_x4t(t0, t1, t2, t3, sVl + off);
                vbl[2 * np][0] = t0; vbl[2 * np][1] = t1;
                vbl[2 * np + 1][0] = t2; vbl[2 * np + 1][1] = t3;
            }
            #pragma unroll
            for (int n = 0; n < 8; n++) {
                mma_bf16(O[n], pa[kb], vbh[n][0], vbh[n][1]);
                mma_bf16(O[n], pa[kb], vbl[n][0], vbl[n][1]);
                mma_bf16(O[n], pb[kb], vbh[n][0], vbh[n][1]);
            }
        }
    }

    // ---- epilogue: O / l -> g_O ----
    float iv0 = 1.f / l0, iv1 = 1.f / l1;
    float* Ob = g_O + (size_t)(b * SEQ + r0g) * 1024 + h * HEAD_DIM;
    #pragma unroll
    for (int n = 0; n < 8; n++) {
        int col = n * 8 + tg * 2;
        *(float2*)(Ob + col) = make_float2(O[n][0] * iv0, O[n][1] * iv0);
        *(float2*)(Ob + 8 * 1024 + col) = make_float2(O[n][2] * iv1, O[n][3] * iv1);
    }
}

// ============================================================
// Launcher
// ============================================================
extern "C" void kernel_launch(void* const* d_in, const int* in_sizes, int n_in,
                              void* d_out, int out_size)
{
    (void)in_sizes; (void)n_in; (void)out_size;
    const float* q  = (const float*)d_in[0];
    const float* k  = (const float*)d_in[1];
    const float* v  = (const float*)d_in[2];
    const float* Wq = (const float*)d_in[4];
    const float* bq = (const float*)d_in[5];
    const float* Wk = (const float*)d_in[6];
    const float* bk = (const float*)d_in[7];
    const float* Wv = (const float*)d_in[8];
    const float* bv = (const float*)d_in[9];
    const float* Wo = (const float*)d_in[10];
    const float* bo = (const float*)d_in[11];
    const float* er = (const float*)d_in[12];

    float* out  = (float*)d_out;             // (B,S,D)
    float* srel = out + OUT_ELEMS;           // (B,H,S,S)
    float* qe   = srel + SREL_ELEMS;         // (B,H,S,S)

    float *Qb, *Kb, *Vb, *Ob;
    cudaGetSymbolAddress((void**)&Qb, g_Q);
    cudaGetSymbolAddress((void**)&Kb, g_K);
    cudaGetSymbolAddress((void**)&Vb, g_V);
    cudaGetSymbolAddress((void**)&Ob, g_O);

    cudaFuncSetAttribute(sgemm_hmma,
                         cudaFuncAttributeMaxDynamicSharedMemorySize, HG_SMEM);
    cudaFuncSetAttribute(qe_hmma,
                         cudaFuncAttributeMaxDynamicSharedMemorySize, QE_SMEM);
    cudaFuncSetAttribute(attn_hmma,
                         cudaFuncAttributeMaxDynamicSharedMemorySize, AT_SMEM);

    dim3 gproj(D_MODEL / 128, ROWS / 128);   // (8, 16)

    sgemm_hmma<<<gproj, 256, HG_SMEM>>>(q, Wq, bq, Qb);
    sgemm_hmma<<<gproj, 256, HG_SMEM>>>(k, Wk, bk, Kb);
    sgemm_hmma<<<gproj, 256, HG_SMEM>>>(v, Wv, bv, Vb);

    qe_hmma<<<dim3(72, BATCH * NUM_HEADS), 256, QE_SMEM>>>(er, qe);
    qe_zero<<<dim3(56, BATCH * NUM_HEADS), 256>>>(qe);

    srel_kernel<<<SREL_ELEMS / 256, 256>>>(qe, srel);

    attn_hmma<<<dim3(8, BATCH * NUM_HEADS), 256, AT_SMEM>>>(srel);

    sgemm_hmma<<<gproj, 256, HG_SMEM>>>(Ob, Wo, bo, out);
}

// round 7
// speedup vs baseline: 2.6834x; 1.0298x over previous
#include <cuda_runtime.h>
#include <cuda_bf16.h>
#include <math.h>
#include <stdint.h>

#define D_MODEL 1024
#define NUM_HEADS 16
#define HEAD_DIM 64
#define SEQ 1024
#define BATCH 2
#define ROWS (BATCH * SEQ)            // 2048
#define OUT_ELEMS   (ROWS * D_MODEL)  // 2,097,152
#define SREL_ELEMS  (BATCH * NUM_HEADS * SEQ * SEQ)  // 33,554,432
#define L2E 1.4426950408889634f

typedef unsigned long long ull;

// ---- HMMA / async helpers (baseline PTX, works on .target sm_103) ----
__device__ __forceinline__ uint32_t smem_u32(const void* p) {
    uint32_t a;
    asm("{ .reg .u64 t; cvta.to.shared.u64 t, %1; cvt.u32.u64 %0, t; }"
        : "=r"(a) : "l"(p));
    return a;
}
__device__ __forceinline__ void cp16(uint32_t dst, const void* src) {
    asm volatile("cp.async.cg.shared.global [%0], [%1], 16;" :: "r"(dst), "l"(src));
}
__device__ __forceinline__ void cp_commit() {
    asm volatile("cp.async.commit_group;" ::: "memory");
}
__device__ __forceinline__ void cp_wait0() {
    asm volatile("cp.async.wait_group 0;" ::: "memory");
}
__device__ __forceinline__ void ldmat_x4(uint32_t& r0, uint32_t& r1,
                                         uint32_t& r2, uint32_t& r3, uint32_t addr) {
    asm volatile("ldmatrix.sync.aligned.m8n8.x4.shared.b16 {%0,%1,%2,%3}, [%4];"
                 : "=r"(r0), "=r"(r1), "=r"(r2), "=r"(r3) : "r"(addr));
}
__device__ __forceinline__ void ldmat_x4t(uint32_t& r0, uint32_t& r1,
                                          uint32_t& r2, uint32_t& r3, uint32_t addr) {
    asm volatile("ldmatrix.sync.aligned.m8n8.x4.trans.shared.b16 {%0,%1,%2,%3}, [%4];"
                 : "=r"(r0), "=r"(r1), "=r"(r2), "=r"(r3) : "r"(addr));
}
__device__ __forceinline__ void ldmat_x2t(uint32_t& r0, uint32_t& r1, uint32_t addr) {
    asm volatile("ldmatrix.sync.aligned.m8n8.x2.trans.shared.b16 {%0,%1}, [%2];"
                 : "=r"(r0), "=r"(r1) : "r"(addr));
}
__device__ __forceinline__ void mma_bf16(float* c, const uint32_t* a,
                                         uint32_t b0, uint32_t b1) {
    asm volatile(
        "mma.sync.aligned.m16n8k16.row.col.f32.bf16.bf16.f32 "
        "{%0,%1,%2,%3}, {%4,%5,%6,%7}, {%8,%9}, {%0,%1,%2,%3};"
        : "+f"(c[0]), "+f"(c[1]), "+f"(c[2]), "+f"(c[3])
        : "r"(a[0]), "r"(a[1]), "r"(a[2]), "r"(a[3]), "r"(b0), "r"(b1));
}
__device__ __forceinline__ float ex2(float x) {
    float r; asm("ex2.approx.f32 %0,%1;" : "=f"(r) : "f"(x)); return r;
}

// bf16 2-way split: x = hi + lo
__device__ __forceinline__ void split2(float x, float y, uint32_t& hi, uint32_t& lo) {
    __nv_bfloat162 h;
    h.x = __float2bfloat16(x);
    h.y = __float2bfloat16(y);
    __nv_bfloat162 l;
    l.x = __float2bfloat16(x - __bfloat162float(h.x));
    l.y = __float2bfloat16(y - __bfloat162float(h.y));
    hi = *(uint32_t*)&h;
    lo = *(uint32_t*)&l;
}

// -------- scratch --------
__device__ float g_Q[ROWS * D_MODEL];
__device__ float g_K[ROWS * D_MODEL];
__device__ float g_V[ROWS * D_MODEL];
__device__ float g_O[ROWS * D_MODEL];

// ============================================================
// HMMA GEMM + bias with cp.async-pipelined staging.
// CTA 128x128, 8 warps (warp tile 32x64), K-chunk 64, bf16 split x3.
// ============================================================
#define AST 72
#define BST 136
#define HG_BF_BYTES ((128 * AST * 2 + 64 * BST * 2) * 2)      // 71680
#define SGA_STG (128 * 68)
#define SGB_STG (64 * 132)
#define HG_SMEM (HG_BF_BYTES + (SGA_STG + SGB_STG) * 4)       // 140288

__global__ __launch_bounds__(256, 1) void sgemm_hmma(
    const float* __restrict__ A, const float* __restrict__ B,
    const float* __restrict__ bias, float* __restrict__ C)
{
    extern __shared__ char smemc[];
    __nv_bfloat16* Ah = (__nv_bfloat16*)smemc;
    __nv_bfloat16* Al = Ah + 128 * AST;
    __nv_bfloat16* Bh = Al + 128 * AST;
    __nv_bfloat16* Bl = Bh + 64 * BST;
    float* stA = (float*)(smemc + HG_BF_BYTES);
    float* stB = stA + SGA_STG;

    const int tid = threadIdx.x;
    const int wid = tid >> 5;
    const int lane = tid & 31;
    const int row0 = blockIdx.y * 128;
    const int col0 = blockIdx.x * 128;
    const int mo = (wid >> 1) * 32;
    const int no = (wid & 1) * 64;

    float acc[2][8][4];
    #pragma unroll
    for (int mi = 0; mi < 2; mi++)
        #pragma unroll
        for (int ni = 0; ni < 8; ni++)
            #pragma unroll
            for (int e = 0; e < 4; e++) acc[mi][ni][e] = 0.f;

    const uint32_t sAh = smem_u32(Ah), sAl = smem_u32(Al);
    const uint32_t sBh = smem_u32(Bh), sBl = smem_u32(Bl);
    const uint32_t uA = smem_u32(stA), uB = smem_u32(stB);

    const int ar = tid >> 4, ac4 = (tid & 15) << 2;   // A cp pattern base
    const int br = tid >> 5, bn4 = (tid & 31) << 2;   // B cp pattern base

    // preload chunk 0
    {
        #pragma unroll
        for (int it = 0; it < 8; it++) {
            int r = ar + it * 16;
            cp16(uA + (r * 68 + ac4) * 4, A + (size_t)(row0 + r) * 1024 + ac4);
        }
        #pragma unroll
        for (int it = 0; it < 8; it++) {
            int r = br + it * 8;
            cp16(uB + (r * 132 + bn4) * 4, B + (size_t)r * 1024 + col0 + bn4);
        }
        cp_commit();
    }
    cp_wait0();
    __syncthreads();

    for (int c = 0; c < 16; c++) {
        // ---- convert staging -> bf16 hi/lo ----
        #pragma unroll
        for (int it = 0; it < 8; it++) {
            int r = ar + it * 16;
            float4 v = *(float4*)(stA + r * 68 + ac4);
            uint32_t h01, l01, h23, l23;
            split2(v.x, v.y, h01, l01);
            split2(v.z, v.w, h23, l23);
            *(uint2*)(Ah + r * AST + ac4) = make_uint2(h01, h23);
            *(uint2*)(Al + r * AST + ac4) = make_uint2(l01, l23);
        }
        #pragma unroll
        for (int it = 0; it < 8; it++) {
            int r = br + it * 8;
            float4 v = *(float4*)(stB + r * 132 + bn4);
            uint32_t h01, l01, h23, l23;
            split2(v.x, v.y, h01, l01);
            split2(v.z, v.w, h23, l23);
            *(uint2*)(Bh + r * BST + bn4) = make_uint2(h01, h23);
            *(uint2*)(Bl + r * BST + bn4) = make_uint2(l01, l23);
        }
        __syncthreads();

        // ---- issue next chunk's cp.async (overlaps with MMA below) ----
        if (c < 15) {
            const int k0 = (c + 1) * 64;
            #pragma unroll
            for (int it = 0; it < 8; it++) {
                int r = ar + it * 16;
                cp16(uA + (r * 68 + ac4) * 4,
                     A + (size_t)(row0 + r) * 1024 + k0 + ac4);
            }
            #pragma unroll
            for (int it = 0; it < 8; it++) {
                int r = br + it * 8;
                cp16(uB + (r * 132 + bn4) * 4,
                     B + (size_t)(k0 + r) * 1024 + col0 + bn4);
            }
            cp_commit();
        }

        // ---- MMA for chunk c ----
        #pragma unroll
        for (int ks = 0; ks < 4; ks++) {
            uint32_t ah[2][4], al[2][4];
            #pragma unroll
            for (int mi = 0; mi < 2; mi++) {
                uint32_t off = ((mo + mi * 16 + (lane & 15)) * AST
                                + ks * 16 + (lane >> 4) * 8) * 2;
                ldmat_x4(ah[mi][0], ah[mi][1], ah[mi][2], ah[mi][3], sAh + off);
                ldmat_x4(al[mi][0], al[mi][1], al[mi][2], al[mi][3], sAl + off);
            }
            #pragma unroll
            for (int ni = 0; ni < 8; ni++) {
                uint32_t offB = ((ks * 16 + (lane & 15)) * BST + no + ni * 8) * 2;
                uint32_t bh0, bh1, bl0, bl1;
                ldmat_x2t(bh0, bh1, sBh + offB);
                ldmat_x2t(bl0, bl1, sBl + offB);
                #pragma unroll
                for (int mi = 0; mi < 2; mi++) {
                    mma_bf16(acc[mi][ni], ah[mi], bh0, bh1);
                    mma_bf16(acc[mi][ni], ah[mi], bl0, bl1);
                    mma_bf16(acc[mi][ni], al[mi], bh0, bh1);
                }
            }
        }
        if (c < 15) cp_wait0();
        __syncthreads();
    }

    const int g = lane >> 2, tg = lane & 3;
    #pragma unroll
    for (int mi = 0; mi < 2; mi++) {
        #pragma unroll
        for (int ni = 0; ni < 8; ni++) {
            int colb = col0 + no + ni * 8 + tg * 2;
            float2 bb = *(const float2*)(bias + colb);
            int r0 = row0 + mo + mi * 16 + g;
            float2 w0 = make_float2(acc[mi][ni][0] + bb.x, acc[mi][ni][1] + bb.y);
            float2 w1 = make_float2(acc[mi][ni][2] + bb.x, acc[mi][ni][3] + bb.y);
            *(float2*)(C + (size_t)r0 * 1024 + colb) = w0;
            *(float2*)(C + (size_t)(r0 + 8) * 1024 + colb) = w1;
        }
    }
}

// ============================================================
// qe via HMMA, banded tiles; ALSO writes the matching S_rel entries
// (S_rel[i,j] = qe[i, 1023-i+j] for j<=i).
// ============================================================
#define KST 72
#define QE_SMEM ((2 * 128 * KST + 2 * 64 * KST) * 2)   // 55296 B

__global__ __launch_bounds__(256, 1) void qe_hmma(
    const float* __restrict__ er, float* __restrict__ qe_out,
    float* __restrict__ srel_out)
{
    extern __shared__ __nv_bfloat16 sh[];
    __nv_bfloat16* Qh = sh;
    __nv_bfloat16* Ql = Qh + 128 * KST;
    __nv_bfloat16* Eh = Ql + 128 * KST;
    __nv_bfloat16* El = Eh + 64 * KST;

    int t = blockIdx.x;              // 0..71
    int a = 0;
    while (t >= 2 * a + 2) { t -= 2 * a + 2; a++; }
    const int c = 14 - 2 * a + t;
    const int i0 = a * 128, k0 = c * 64;
    const int bh = blockIdx.y;
    const int b = bh >> 4, h = bh & 15;
    const int tid = threadIdx.x;
    const int wid = tid >> 5;
    const int lane = tid & 31;
    const int g = lane >> 2, tg = lane & 3;
    const int mo = wid * 16;

    const float* Qg = g_Q + (size_t)(b * SEQ) * D_MODEL + h * HEAD_DIM;

    #pragma unroll
    for (int it = 0; it < 8; it++) {
        int idx = tid + it * 256;
        int r = idx >> 4, c4 = (idx & 15) << 2;
        float4 v = *(const float4*)(Qg + (size_t)(i0 + r) * 1024 + c4);
        uint32_t h01, l01, h23, l23;
        split2(v.x, v.y, h01, l01);
        split2(v.z, v.w, h23, l23);
        *(uint2*)(Qh + r * KST + c4) = make_uint2(h01, h23);
        *(uint2*)(Ql + r * KST + c4) = make_uint2(l01, l23);
    }
    #pragma unroll
    for (int it = 0; it < 4; it++) {
        int idx = tid + it * 256;
        int r = idx >> 4, c4 = (idx & 15) << 2;
        float4 v = *(const float4*)(er + (size_t)(k0 + r) * HEAD_DIM + c4);
        uint32_t h01, l01, h23, l23;
        split2(v.x, v.y, h01, l01);
        split2(v.z, v.w, h23, l23);
        *(uint2*)(Eh + r * KST + c4) = make_uint2(h01, h23);
        *(uint2*)(El + r * KST + c4) = make_uint2(l01, l23);
    }
    __syncthreads();

    const uint32_t sQh = smem_u32(Qh), sQl = smem_u32(Ql);
    const uint32_t sEh = smem_u32(Eh), sEl = smem_u32(El);

    uint32_t qh[4][4], ql[4][4];
    #pragma unroll
    for (int kb = 0; kb < 4; kb++) {
        uint32_t off = ((mo + (lane & 15)) * KST + kb * 16 + (lane >> 4) * 8) * 2;
        ldmat_x4(qh[kb][0], qh[kb][1], qh[kb][2], qh[kb][3], sQh + off);
        ldmat_x4(ql[kb][0], ql[kb][1], ql[kb][2], ql[kb][3], sQl + off);
    }

    float sa[8][4];
    #pragma unroll
    for (int n = 0; n < 8; n++)
        #pragma unroll
        for (int e = 0; e < 4; e++) sa[n][e] = 0.f;

    #pragma unroll
    for (int ks = 0; ks < 4; ks++) {
        uint32_t ebh[8][2], ebl[8][2];
        #pragma unroll
        for (int np = 0; np < 4; np++) {
            uint32_t off = ((np * 16 + ((lane >> 4) << 3) + (lane & 7)) * KST
                            + ks * 16 + ((lane >> 3) & 1) * 8) * 2;
            uint32_t t0, t1, t2, t3;
            ldmat_x4(t0, t1, t2, t3, sEh + off);
            ebh[2 * np][0] = t0; ebh[2 * np][1] = t1;
            ebh[2 * np + 1][0] = t2; ebh[2 * np + 1][1] = t3;
            ldmat_x4(t0, t1, t2, t3, sEl + off);
            ebl[2 * np][0] = t0; ebl[2 * np][1] = t1;
            ebl[2 * np + 1][0] = t2; ebl[2 * np + 1][1] = t3;
        }
        #pragma unroll
        for (int n = 0; n < 8; n++) {
            mma_bf16(sa[n], qh[ks], ebh[n][0], ebh[n][1]);
            mma_bf16(sa[n], qh[ks], ebl[n][0], ebl[n][1]);
            mma_bf16(sa[n], ql[ks], ebh[n][0], ebh[n][1]);
        }
    }

    const int r0g = i0 + mo + g;
    const int r1g = r0g + 8;
    float* outp = qe_out + ((size_t)bh << 20);
    float* srq = srel_out + ((size_t)bh << 20);
    #pragma unroll
    for (int n = 0; n < 8; n++) {
        int col = k0 + n * 8 + tg * 2;
        float2 w0, w1;
        bool a0 = (col     >= 1023 - r0g);
        bool a1 = (col + 1 >= 1023 - r0g);
        bool a2 = (col     >= 1023 - r1g);
        bool a3 = (col + 1 >= 1023 - r1g);
        w0.x = a0 ? sa[n][0] : 0.f;
        w0.y = a1 ? sa[n][1] : 0.f;
        w1.x = a2 ? sa[n][2] : 0.f;
        w1.y = a3 ? sa[n][3] : 0.f;
        *(float2*)(outp + ((size_t)r0g << 10) + col) = w0;
        *(float2*)(outp + ((size_t)r1g << 10) + col) = w1;
        // fused S_rel stores: srel[i, col - 1023 + i] = value
        if (a0) srq[((size_t)r0g << 10) + col     - 1023 + r0g] = sa[n][0];
        if (a1) srq[((size_t)r0g << 10) + col + 1 - 1023 + r0g] = sa[n][1];
        if (a2) srq[((size_t)r1g << 10) + col     - 1023 + r1g] = sa[n][2];
        if (a3) srq[((size_t)r1g << 10) + col + 1 - 1023 + r1g] = sa[n][3];
    }
}

// zero-fill the 56 all-zero qe tiles per bh
__global__ __launch_bounds__(256) void qe_zero(float* __restrict__ qe_out)
{
    int t = blockIdx.x;              // 0..55
    int a = 0;
    while (t >= 14 - 2 * a) { t -= 14 - 2 * a; a++; }
    const int i0 = a * 128, k0 = t * 64;
    const int bh = blockIdx.y;
    float* outp = qe_out + ((size_t)bh << 20);
    const float4 z = make_float4(0.f, 0.f, 0.f, 0.f);
    for (int idx = threadIdx.x; idx < 2048; idx += 256) {
        int r = idx >> 4, k4 = (idx & 15) << 2;
        *(float4*)(outp + ((size_t)(i0 + r) << 10) + k0 + k4) = z;
    }
}

// zero S_rel strict upper triangle (j > i)
__global__ __launch_bounds__(256) void srel_zero(float* __restrict__ srel)
{
    const int i0 = blockIdx.x * 64;
    float* srp = srel + ((size_t)blockIdx.y << 20);
    const int t = threadIdx.x;
    const float4 z = make_float4(0.f, 0.f, 0.f, 0.f);
    for (int r = 0; r < 64; r++) {
        int i = i0 + r;
        float* row = srp + ((size_t)i << 10);
        int jb = i + 1;
        int ja = (jb + 3) & ~3;
        if (t < ja - jb && jb + t < 1024) row[jb + t] = 0.f;
        int j4 = ja + (t << 2);
        if (j4 < 1024) *(float4*)(row + j4) = z;
    }
}

// ============================================================
// Flash attention via HMMA (unchanged from R6 — proven).
// ============================================================
#define AT_SMEM ((2 * 128 * KST + 4 * 64 * KST) * 2)   // 73728 B

__global__ __launch_bounds__(256, 1) void attn_hmma(const float* __restrict__ srel)
{
    extern __shared__ __nv_bfloat16 sh[];
    __nv_bfloat16* Qh = sh;
    __nv_bfloat16* Ql = Qh + 128 * KST;
    __nv_bfloat16* Kh = Ql + 128 * KST;
    __nv_bfloat16* Kl = Kh + 64 * KST;
    __nv_bfloat16* Vh = Kl + 64 * KST;
    __nv_bfloat16* Vl = Vh + 64 * KST;

    const int tid = threadIdx.x;
    const int wid = tid >> 5;
    const int lane = tid & 31;
    const int g = lane >> 2, tg = lane & 3;
    const int a = 7 - blockIdx.x;
    const int i0 = a * 128;
    const int bh = blockIdx.y;
    const int b = bh >> 4, h = bh & 15;
    const int mo = wid * 16;
    const int njt = 2 * a + 2;

    const float* Qg = g_Q + (size_t)(b * SEQ) * D_MODEL + h * HEAD_DIM;
    const float* Kg = g_K + (size_t)(b * SEQ) * D_MODEL + h * HEAD_DIM;
    const float* Vg = g_V + (size_t)(b * SEQ) * D_MODEL + h * HEAD_DIM;
    const float* srp = srel + ((size_t)bh << 20);

    #pragma unroll
    for (int it = 0; it < 8; it++) {
        int idx = tid + it * 256;
        int r = idx >> 4, c4 = (idx & 15) << 2;
        float4 v = *(const float4*)(Qg + (size_t)(i0 + r) * 1024 + c4);
        uint32_t h01, l01, h23, l23;
        split2(v.x, v.y, h01, l01);
        split2(v.z, v.w, h23, l23);
        *(uint2*)(Qh + r * KST + c4) = make_uint2(h01, h23);
        *(uint2*)(Ql + r * KST + c4) = make_uint2(l01, l23);
    }
    __syncthreads();

    const uint32_t sQh = smem_u32(Qh), sQl = smem_u32(Ql);
    const uint32_t sKh = smem_u32(Kh), sKl = smem_u32(Kl);
    const uint32_t sVh = smem_u32(Vh), sVl = smem_u32(Vl);

    uint32_t qh[4][4], ql[4][4];
    #pragma unroll
    for (int kb = 0; kb < 4; kb++) {
        uint32_t off = ((mo + (lane & 15)) * KST + kb * 16 + (lane >> 4) * 8) * 2;
        ldmat_x4(qh[kb][0], qh[kb][1], qh[kb][2], qh[kb][3], sQh + off);
        ldmat_x4(ql[kb][0], ql[kb][1], ql[kb][2], ql[kb][3], sQl + off);
    }

    float O[8][4];
    #pragma unroll
    for (int n = 0; n < 8; n++)
        #pragma unroll
        for (int e = 0; e < 4; e++) O[n][e] = 0.f;
    float m0 = -1e30f, m1 = -1e30f, l0 = 0.f, l1 = 0.f;

    const int r0g = i0 + mo + g;
    const int r1g = r0g + 8;

    for (int t = 0; t < njt; t++) {
        const int j0 = t * 64;
        __syncthreads();
        #pragma unroll
        for (int it = 0; it < 4; it++) {
            int idx = tid + it * 256;
            int r = idx >> 4, c4 = (idx & 15) << 2;
            float4 kv = *(const float4*)(Kg + (size_t)(j0 + r) * 1024 + c4);
            float4 vv = *(const float4*)(Vg + (size_t)(j0 + r) * 1024 + c4);
            uint32_t h01, l01, h23, l23;
            split2(kv.x, kv.y, h01, l01);
            split2(kv.z, kv.w, h23, l23);
            *(uint2*)(Kh + r * KST + c4) = make_uint2(h01, h23);
            *(uint2*)(Kl + r * KST + c4) = make_uint2(l01, l23);
            split2(vv.x, vv.y, h01, l01);
            split2(vv.z, vv.w, h23, l23);
            *(uint2*)(Vh + r * KST + c4) = make_uint2(h01, h23);
            *(uint2*)(Vl + r * KST + c4) = make_uint2(l01, l23);
        }
        __syncthreads();

        if (i0 + mo + 15 < j0) continue;

        float sa[8][4];
        #pragma unroll
        for (int n = 0; n < 8; n++)
            #pragma unroll
            for (int e = 0; e < 4; e++) sa[n][e] = 0.f;
        #pragma unroll
        for (int ks = 0; ks < 4; ks++) {
            uint32_t kbh[8][2], kbl[8][2];
            #pragma unroll
            for (int np = 0; np < 4; np++) {
                uint32_t off = ((np * 16 + ((lane >> 4) << 3) + (lane & 7)) * KST
                                + ks * 16 + ((lane >> 3) & 1) * 8) * 2;
                uint32_t t0, t1, t2, t3;
                ldmat_x4(t0, t1, t2, t3, sKh + off);
                kbh[2 * np][0] = t0; kbh[2 * np][1] = t1;
                kbh[2 * np + 1][0] = t2; kbh[2 * np + 1][1] = t3;
                ldmat_x4(t0, t1, t2, t3, sKl + off);
                kbl[2 * np][0] = t0; kbl[2 * np][1] = t1;
                kbl[2 * np + 1][0] = t2; kbl[2 * np + 1][1] = t3;
            }
            #pragma unroll
            for (int n = 0; n < 8; n++) {
                mma_bf16(sa[n], qh[ks], kbh[n][0], kbh[n][1]);
                mma_bf16(sa[n], qh[ks], kbl[n][0], kbl[n][1]);
                mma_bf16(sa[n], ql[ks], kbh[n][0], kbh[n][1]);
            }
        }

        float tm0 = -1e30f, tm1 = -1e30f;
        #pragma unroll
        for (int n = 0; n < 8; n++) {
            int col = j0 + n * 8 + tg * 2;
            float2 e0 = *(const float2*)(srp + ((size_t)r0g << 10) + col);
            float2 e1 = *(const float2*)(srp + ((size_t)r1g << 10) + col);
            sa[n][0] = (col     <= r0g) ? sa[n][0] * 0.125f + e0.x : -1e30f;
            sa[n][1] = (col + 1 <= r0g) ? sa[n][1] * 0.125f + e0.y : -1e30f;
            sa[n][2] = (col     <= r1g) ? sa[n][2] * 0.125f + e1.x : -1e30f;
            sa[n][3] = (col + 1 <= r1g) ? sa[n][3] * 0.125f + e1.y : -1e30f;
            tm0 = fmaxf(tm0, fmaxf(sa[n][0], sa[n][1]));
            tm1 = fmaxf(tm1, fmaxf(sa[n][2], sa[n][3]));
        }
        tm0 = fmaxf(tm0, __shfl_xor_sync(0xffffffffu, tm0, 1));
        tm0 = fmaxf(tm0, __shfl_xor_sync(0xffffffffu, tm0, 2));
        tm1 = fmaxf(tm1, __shfl_xor_sync(0xffffffffu, tm1, 1));
        tm1 = fmaxf(tm1, __shfl_xor_sync(0xffffffffu, tm1, 2));
        float nm0 = fmaxf(m0, tm0), nm1 = fmaxf(m1, tm1);
        float al0 = ex2((m0 - nm0) * L2E), al1 = ex2((m1 - nm1) * L2E);
        m0 = nm0; m1 = nm1;

        float rs0 = 0.f, rs1 = 0.f;
        #pragma unroll
        for (int n = 0; n < 8; n++) {
            sa[n][0] = ex2((sa[n][0] - nm0) * L2E);
            sa[n][1] = ex2((sa[n][1] - nm0) * L2E);
            sa[n][2] = ex2((sa[n][2] - nm1) * L2E);
            sa[n][3] = ex2((sa[n][3] - nm1) * L2E);
            rs0 += sa[n][0] + sa[n][1];
            rs1 += sa[n][2] + sa[n][3];
        }
        rs0 += __shfl_xor_sync(0xffffffffu, rs0, 1);
        rs0 += __shfl_xor_sync(0xffffffffu, rs0, 2);
        rs1 += __shfl_xor_sync(0xffffffffu, rs1, 1);
        rs1 += __shfl_xor_sync(0xffffffffu, rs1, 2);
        l0 = l0 * al0 + rs0;
        l1 = l1 * al1 + rs1;

        #pragma unroll
        for (int n = 0; n < 8; n++) {
            O[n][0] *= al0; O[n][1] *= al0;
            O[n][2] *= al1; O[n][3] *= al1;
        }

        uint32_t pa[4][4], pb[4][4];
        #pragma unroll
        for (int kb = 0; kb < 4; kb++) {
            split2(sa[2 * kb][0],     sa[2 * kb][1],     pa[kb][0], pb[kb][0]);
            split2(sa[2 * kb][2],     sa[2 * kb][3],     pa[kb][1], pb[kb][1]);
            split2(sa[2 * kb + 1][0], sa[2 * kb + 1][1], pa[kb][2], pb[kb][2]);
            split2(sa[2 * kb + 1][2], sa[2 * kb + 1][3], pa[kb][3], pb[kb][3]);
        }

        #pragma unroll
        for (int kb = 0; kb < 4; kb++) {
            uint32_t vbh[8][2], vbl[8][2];
            #pragma unroll
            for (int np = 0; np < 4; np++) {
                uint32_t off = ((kb * 16 + (lane & 15)) * KST
                                + np * 16 + ((lane >> 4) << 3)) * 2;
                uint32_t t0, t1, t2, t3;
                ldmat_x4t(t0, t1, t2, t3, sVh + off);
                vbh[2 * np][0] = t0; vbh[2 * np][1] = t1;
                vbh[2 * np + 1][0] = t2; vbh[2 * np + 1][1] = t3;
                ldmat_x4t(t0, t1, t2, t3, sVl + off);
                vbl[2 * np][0] = t0; vbl[2 * np][1] = t1;
                vbl[2 * np + 1][0] = t2; vbl[2 * np + 1][1] = t3;
            }
            #pragma unroll
            for (int n = 0; n < 8; n++) {
                mma_bf16(O[n], pa[kb], vbh[n][0], vbh[n][1]);
                mma_bf16(O[n], pa[kb], vbl[n][0], vbl[n][1]);
                mma_bf16(O[n], pb[kb], vbh[n][0], vbh[n][1]);
            }
        }
    }

    float iv0 = 1.f / l0, iv1 = 1.f / l1;
    float* Ob = g_O + (size_t)(b * SEQ + r0g) * 1024 + h * HEAD_DIM;
    #pragma unroll
    for (int n = 0; n < 8; n++) {
        int col = n * 8 + tg * 2;
        *(float2*)(Ob + col) = make_float2(O[n][0] * iv0, O[n][1] * iv0);
        *(float2*)(Ob + 8 * 1024 + col) = make_float2(O[n][2] * iv1, O[n][3] * iv1);
    }
}

// ============================================================
// Launcher
// ============================================================
extern "C" void kernel_launch(void* const* d_in, const int* in_sizes, int n_in,
                              void* d_out, int out_size)
{
    (void)in_sizes; (void)n_in; (void)out_size;
    const float* q  = (const float*)d_in[0];
    const float* k  = (const float*)d_in[1];
    const float* v  = (const float*)d_in[2];
    const float* Wq = (const float*)d_in[4];
    const float* bq = (const float*)d_in[5];
    const float* Wk = (const float*)d_in[6];
    const float* bk = (const float*)d_in[7];
    const float* Wv = (const float*)d_in[8];
    const float* bv = (const float*)d_in[9];
    const float* Wo = (const float*)d_in[10];
    const float* bo = (const float*)d_in[11];
    const float* er = (const float*)d_in[12];

    float* out  = (float*)d_out;             // (B,S,D)
    float* srel = out + OUT_ELEMS;           // (B,H,S,S)
    float* qe   = srel + SREL_ELEMS;         // (B,H,S,S)

    float *Qb, *Kb, *Vb, *Ob;
    cudaGetSymbolAddress((void**)&Qb, g_Q);
    cudaGetSymbolAddress((void**)&Kb, g_K);
    cudaGetSymbolAddress((void**)&Vb, g_V);
    cudaGetSymbolAddress((void**)&Ob, g_O);

    cudaFuncSetAttribute(sgemm_hmma,
                         cudaFuncAttributeMaxDynamicSharedMemorySize, HG_SMEM);
    cudaFuncSetAttribute(qe_hmma,
                         cudaFuncAttributeMaxDynamicSharedMemorySize, QE_SMEM);
    cudaFuncSetAttribute(attn_hmma,
                         cudaFuncAttributeMaxDynamicSharedMemorySize, AT_SMEM);

    dim3 gproj(D_MODEL / 128, ROWS / 128);   // (8, 16)

    sgemm_hmma<<<gproj, 256, HG_SMEM>>>(q, Wq, bq, Qb);
    sgemm_hmma<<<gproj, 256, HG_SMEM>>>(k, Wk, bk, Kb);
    sgemm_hmma<<<gproj, 256, HG_SMEM>>>(v, Wv, bv, Vb);

    qe_hmma<<<dim3(72, BATCH * NUM_HEADS), 256, QE_SMEM>>>(er, qe, srel);
    qe_zero<<<dim3(56, BATCH * NUM_HEADS), 256>>>(qe);
    srel_zero<<<dim3(16, BATCH * NUM_HEADS), 256>>>(srel);

    attn_hmma<<<dim3(8, BATCH * NUM_HEADS), 256, AT_SMEM>>>(srel);

    sgemm_hmma<<<gproj, 256, HG_SMEM>>>(Ob, Wo, bo, out);
}

// round 10
// speedup vs baseline: 3.0511x; 1.1370x over previous
#include <cuda_runtime.h>
#include <cuda_bf16.h>
#include <math.h>
#include <stdint.h>

#define D_MODEL 1024
#define NUM_HEADS 16
#define HEAD_DIM 64
#define SEQ 1024
#define BATCH 2
#define ROWS (BATCH * SEQ)            // 2048
#define OUT_ELEMS   (ROWS * D_MODEL)  // 2,097,152
#define SREL_ELEMS  (BATCH * NUM_HEADS * SEQ * SEQ)  // 33,554,432
#define L2E 1.4426950408889634f

// ---- helpers ----
__device__ __forceinline__ uint32_t smem_u32(const void* p) {
    uint32_t a;
    asm("{ .reg .u64 t; cvta.to.shared.u64 t, %1; cvt.u32.u64 %0, t; }"
        : "=r"(a) : "l"(p));
    return a;
}
__device__ __forceinline__ void cp16(uint32_t dst, const void* src) {
    asm volatile("cp.async.cg.shared.global [%0], [%1], 16;" :: "r"(dst), "l"(src));
}
__device__ __forceinline__ void cp_commit() {
    asm volatile("cp.async.commit_group;" ::: "memory");
}
__device__ __forceinline__ void cp_wait0() {
    asm volatile("cp.async.wait_group 0;" ::: "memory");
}
__device__ __forceinline__ void cp_wait1() {
    asm volatile("cp.async.wait_group 1;" ::: "memory");
}
__device__ __forceinline__ void ldmat_x4(uint32_t& r0, uint32_t& r1,
                                         uint32_t& r2, uint32_t& r3, uint32_t addr) {
    asm volatile("ldmatrix.sync.aligned.m8n8.x4.shared.b16 {%0,%1,%2,%3}, [%4];"
                 : "=r"(r0), "=r"(r1), "=r"(r2), "=r"(r3) : "r"(addr));
}
__device__ __forceinline__ void ldmat_x4t(uint32_t& r0, uint32_t& r1,
                                          uint32_t& r2, uint32_t& r3, uint32_t addr) {
    asm volatile("ldmatrix.sync.aligned.m8n8.x4.trans.shared.b16 {%0,%1,%2,%3}, [%4];"
                 : "=r"(r0), "=r"(r1), "=r"(r2), "=r"(r3) : "r"(addr));
}
__device__ __forceinline__ void ldmat_x2t(uint32_t& r0, uint32_t& r1, uint32_t addr) {
    asm volatile("ldmatrix.sync.aligned.m8n8.x2.trans.shared.b16 {%0,%1}, [%2];"
                 : "=r"(r0), "=r"(r1) : "r"(addr));
}
__device__ __forceinline__ void mma_bf16(float* c, const uint32_t* a,
                                         uint32_t b0, uint32_t b1) {
    asm volatile(
        "mma.sync.aligned.m16n8k16.row.col.f32.bf16.bf16.f32 "
        "{%0,%1,%2,%3}, {%4,%5,%6,%7}, {%8,%9}, {%0,%1,%2,%3};"
        : "+f"(c[0]), "+f"(c[1]), "+f"(c[2]), "+f"(c[3])
        : "r"(a[0]), "r"(a[1]), "r"(a[2]), "r"(a[3]), "r"(b0), "r"(b1));
}
__device__ __forceinline__ float ex2(float x) {
    float r; asm("ex2.approx.f32 %0,%1;" : "=f"(r) : "f"(x)); return r;
}
__device__ __forceinline__ void split2(float x, float y, uint32_t& hi, uint32_t& lo) {
    __nv_bfloat162 h;
    h.x = __float2bfloat16(x);
    h.y = __float2bfloat16(y);
    __nv_bfloat162 l;
    l.x = __float2bfloat16(x - __bfloat162float(h.x));
    l.y = __float2bfloat16(y - __bfloat162float(h.y));
    hi = *(uint32_t*)&h;
    lo = *(uint32_t*)&l;
}

// -------- persistent split scratch --------
__device__ __nv_bfloat16 g_qh[OUT_ELEMS], g_ql[OUT_ELEMS];
__device__ __nv_bfloat16 g_kh[OUT_ELEMS], g_kl[OUT_ELEMS];
__device__ __nv_bfloat16 g_vh[OUT_ELEMS], g_vl[OUT_ELEMS];
__device__ __nv_bfloat16 g_Wqh[D_MODEL * D_MODEL], g_Wql[D_MODEL * D_MODEL];
__device__ __nv_bfloat16 g_Wkh[D_MODEL * D_MODEL], g_Wkl[D_MODEL * D_MODEL];
__device__ __nv_bfloat16 g_Wvh[D_MODEL * D_MODEL], g_Wvl[D_MODEL * D_MODEL];
__device__ __nv_bfloat16 g_Woh[D_MODEL * D_MODEL], g_Wol[D_MODEL * D_MODEL];
__device__ __nv_bfloat16 g_Qh[OUT_ELEMS], g_Ql[OUT_ELEMS];
__device__ __nv_bfloat16 g_Kh[OUT_ELEMS], g_Kl[OUT_ELEMS];
__device__ __nv_bfloat16 g_Vh[OUT_ELEMS], g_Vl[OUT_ELEMS];
__device__ __nv_bfloat16 g_Oh[OUT_ELEMS], g_Ol[OUT_ELEMS];

// ============================================================
// f32 -> bf16 hi/lo split (elementwise, vectorized)
// ============================================================
__global__ __launch_bounds__(256) void cvt_split(
    const float* __restrict__ s, __nv_bfloat16* __restrict__ hi,
    __nv_bfloat16* __restrict__ lo)
{
    int i = blockIdx.x * 256 + threadIdx.x;
    float4 v = ((const float4*)s)[i];
    uint32_t h01, l01, h23, l23;
    split2(v.x, v.y, h01, l01);
    split2(v.z, v.w, h23, l23);
    ((uint2*)hi)[i] = make_uint2(h01, h23);
    ((uint2*)lo)[i] = make_uint2(l01, l23);
}

// ============================================================
// Pure-bf16 HMMA GEMM: C = A @ B + bias; A/B pre-split hi/lo.
// CTA 128x128, 8 warps, K-chunk 64, cp.async double-buffered.
// Epilogue: f32 (Cf) or split bf16 (Ch/Cl).
// ============================================================
#define AST 72
#define BST 136
#define GB_A_BYTES (128 * AST * 2)      // 18432
#define GB_B_BYTES (64 * BST * 2)       // 17408
#define GB_STAGE (2 * GB_A_BYTES + 2 * GB_B_BYTES)   // 71680
#define GB_SMEM (2 * GB_STAGE)                       // 143360

__global__ __launch_bounds__(256, 1) void gemm_bf(
    const __nv_bfloat16* __restrict__ Ahg, const __nv_bfloat16* __restrict__ Alg,
    const __nv_bfloat16* __restrict__ Bhg, const __nv_bfloat16* __restrict__ Blg,
    const float* __restrict__ bias, float* __restrict__ Cf,
    __nv_bfloat16* __restrict__ Ch, __nv_bfloat16* __restrict__ Cl)
{
    extern __shared__ char smemc[];
    const uint32_t sb = smem_u32(smemc);
    const int tid = threadIdx.x;
    const int wid = tid >> 5;
    const int lane = tid & 31;
    const int row0 = blockIdx.y * 128;
    const int col0 = blockIdx.x * 128;
    const int mo = (wid >> 1) * 32;
    const int no = (wid & 1) * 64;

    float acc[2][8][4];
    #pragma unroll
    for (int mi = 0; mi < 2; mi++)
        #pragma unroll
        for (int ni = 0; ni < 8; ni++)
            #pragma unroll
            for (int e = 0; e < 4; e++) acc[mi][ni][e] = 0.f;

    auto load_chunk = [&](int c, int s) {
        uint32_t base = sb + s * GB_STAGE;
        const int k0 = c * 64;
        #pragma unroll
        for (int it = 0; it < 4; it++) {
            int idx = tid + it * 256;
            int r = idx >> 3, sg = idx & 7;
            size_t go = (size_t)(row0 + r) * 1024 + k0 + sg * 8;
            uint32_t so = r * 144 + sg * 16;
            cp16(base + so, Ahg + go);
            cp16(base + GB_A_BYTES + so, Alg + go);
        }
        #pragma unroll
        for (int it = 0; it < 4; it++) {
            int idx = tid + it * 256;
            int r = idx >> 4, sg = idx & 15;
            size_t go = (size_t)(k0 + r) * 1024 + col0 + sg * 8;
            uint32_t so = r * 272 + sg * 16;
            cp16(base + 2 * GB_A_BYTES + so, Bhg + go);
            cp16(base + 2 * GB_A_BYTES + GB_B_BYTES + so, Blg + go);
        }
        cp_commit();
    };

    load_chunk(0, 0);

    for (int c = 0; c < 16; c++) {
        const int s = c & 1;
        if (c + 1 < 16) { load_chunk(c + 1, s ^ 1); cp_wait1(); }
        else cp_wait0();
        __syncthreads();

        const uint32_t sAh = sb + s * GB_STAGE;
        const uint32_t sAl = sAh + GB_A_BYTES;
        const uint32_t sBh = sAh + 2 * GB_A_BYTES;
        const uint32_t sBl = sBh + GB_B_BYTES;

        #pragma unroll
        for (int ks = 0; ks < 4; ks++) {
            uint32_t ah[2][4], al[2][4];
            #pragma unroll
            for (int mi = 0; mi < 2; mi++) {
                uint32_t off = ((mo + mi * 16 + (lane & 15)) * AST
                                + ks * 16 + (lane >> 4) * 8) * 2;
                ldmat_x4(ah[mi][0], ah[mi][1], ah[mi][2], ah[mi][3], sAh + off);
                ldmat_x4(al[mi][0], al[mi][1], al[mi][2], al[mi][3], sAl + off);
            }
            #pragma unroll
            for (int ni = 0; ni < 8; ni++) {
                uint32_t offB = ((ks * 16 + (lane & 15)) * BST + no + ni * 8) * 2;
                uint32_t bh0, bh1, bl0, bl1;
                ldmat_x2t(bh0, bh1, sBh + offB);
                ldmat_x2t(bl0, bl1, sBl + offB);
                #pragma unroll
                for (int mi = 0; mi < 2; mi++) {
                    mma_bf16(acc[mi][ni], ah[mi], bh0, bh1);
                    mma_bf16(acc[mi][ni], ah[mi], bl0, bl1);
                    mma_bf16(acc[mi][ni], al[mi], bh0, bh1);
                }
            }
        }
        __syncthreads();
    }

    const int g = lane >> 2, tg = lane & 3;
    #pragma unroll
    for (int mi = 0; mi < 2; mi++) {
        #pragma unroll
        for (int ni = 0; ni < 8; ni++) {
            int colb = col0 + no + ni * 8 + tg * 2;
            float2 bb = *(const float2*)(bias + colb);
            int r0 = row0 + mo + mi * 16 + g;
            float w0x = acc[mi][ni][0] + bb.x, w0y = acc[mi][ni][1] + bb.y;
            float w1x = acc[mi][ni][2] + bb.x, w1y = acc[mi][ni][3] + bb.y;
            if (Cf) {
                *(float2*)(Cf + (size_t)r0 * 1024 + colb) = make_float2(w0x, w0y);
                *(float2*)(Cf + (size_t)(r0 + 8) * 1024 + colb) = make_float2(w1x, w1y);
            } else {
                uint32_t h0, l0, h1, l1;
                split2(w0x, w0y, h0, l0);
                split2(w1x, w1y, h1, l1);
                *(uint32_t*)(Ch + (size_t)r0 * 1024 + colb) = h0;
                *(uint32_t*)(Cl + (size_t)r0 * 1024 + colb) = l0;
                *(uint32_t*)(Ch + (size_t)(r0 + 8) * 1024 + colb) = h1;
                *(uint32_t*)(Cl + (size_t)(r0 + 8) * 1024 + colb) = l1;
            }
        }
    }
}

// ============================================================
// qe via HMMA from pre-split Q; fused S_rel stores.
// ============================================================
#define KST 72
#define QE_SMEM ((2 * 128 * KST + 2 * 64 * KST) * 2)   // 55296 B

__global__ __launch_bounds__(256, 1) void qe_hmma(
    const float* __restrict__ er, float* __restrict__ qe_out,
    float* __restrict__ srel_out)
{
    extern __shared__ __nv_bfloat16 sh[];
    __nv_bfloat16* Qh = sh;
    __nv_bfloat16* Ql = Qh + 128 * KST;
    __nv_bfloat16* Eh = Ql + 128 * KST;
    __nv_bfloat16* El = Eh + 64 * KST;

    int t = blockIdx.x;              // 0..71
    int a = 0;
    while (t >= 2 * a + 2) { t -= 2 * a + 2; a++; }
    const int c = 14 - 2 * a + t;
    const int i0 = a * 128, k0 = c * 64;
    const int bh = blockIdx.y;
    const int b = bh >> 4, h = bh & 15;
    const int tid = threadIdx.x;
    const int wid = tid >> 5;
    const int lane = tid & 31;
    const int g = lane >> 2, tg = lane & 3;
    const int mo = wid * 16;
    const int bS = b * SEQ;

    // Q tile from pre-split arrays
    #pragma unroll
    for (int it = 0; it < 4; it++) {
        int idx = tid + it * 256;
        int r = idx >> 3, sg = idx & 7;
        size_t go = (size_t)(bS + i0 + r) * 1024 + h * 64 + sg * 8;
        *(uint4*)((char*)Qh + r * 144 + sg * 16) = *(const uint4*)(g_Qh + go);
        *(uint4*)((char*)Ql + r * 144 + sg * 16) = *(const uint4*)(g_Ql + go);
    }
    // E tile (f32, split)
    #pragma unroll
    for (int it = 0; it < 4; it++) {
        int idx = tid + it * 256;
        int r = idx >> 4, c4 = (idx & 15) << 2;
        float4 v = *(const float4*)(er + (size_t)(k0 + r) * HEAD_DIM + c4);
        uint32_t h01, l01, h23, l23;
        split2(v.x, v.y, h01, l01);
        split2(v.z, v.w, h23, l23);
        *(uint2*)(Eh + r * KST + c4) = make_uint2(h01, h23);
        *(uint2*)(El + r * KST + c4) = make_uint2(l01, l23);
    }
    __syncthreads();

    const uint32_t sQh = smem_u32(Qh), sQl = smem_u32(Ql);
    const uint32_t sEh = smem_u32(Eh), sEl = smem_u32(El);

    uint32_t qh[4][4], ql[4][4];
    #pragma unroll
    for (int kb = 0; kb < 4; kb++) {
        uint32_t off = ((mo + (lane & 15)) * KST + kb * 16 + (lane >> 4) * 8) * 2;
        ldmat_x4(qh[kb][0], qh[kb][1], qh[kb][2], qh[kb][3], sQh + off);
        ldmat_x4(ql[kb][0], ql[kb][1], ql[kb][2], ql[kb][3], sQl + off);
    }

    float sa[8][4];
    #pragma unroll
    for (int n = 0; n < 8; n++)
        #pragma unroll
        for (int e = 0; e < 4; e++) sa[n][e] = 0.f;

    #pragma unroll
    for (int ks = 0; ks < 4; ks++) {
        uint32_t ebh[8][2], ebl[8][2];
        #pragma unroll
        for (int np = 0; np < 4; np++) {
            uint32_t off = ((np * 16 + ((lane >> 4) << 3) + (lane & 7)) * KST
                            + ks * 16 + ((lane >> 3) & 1) * 8) * 2;
            uint32_t t0, t1, t2, t3;
            ldmat_x4(t0, t1, t2, t3, sEh + off);
            ebh[2 * np][0] = t0; ebh[2 * np][1] = t1;
            ebh[2 * np + 1][0] = t2; ebh[2 * np + 1][1] = t3;
            ldmat_x4(t0, t1, t2, t3, sEl + off);
            ebl[2 * np][0] = t0; ebl[2 * np][1] = t1;
            ebl[2 * np + 1][0] = t2; ebl[2 * np + 1][1] = t3;
        }
        #pragma unroll
        for (int n = 0; n < 8; n++) {
            mma_bf16(sa[n], qh[ks], ebh[n][0], ebh[n][1]);
            mma_bf16(sa[n], qh[ks], ebl[n][0], ebl[n][1]);
            mma_bf16(sa[n], ql[ks], ebh[n][0], ebh[n][1]);
        }
    }

    const int r0g = i0 + mo + g;
    const int r1g = r0g + 8;
    float* outp = qe_out + ((size_t)bh << 20);
    float* srq = srel_out + ((size_t)bh << 20);
    #pragma unroll
    for (int n = 0; n < 8; n++) {
        int col = k0 + n * 8 + tg * 2;
        float2 w0, w1;
        bool a0 = (col     >= 1023 - r0g);
        bool a1 = (col + 1 >= 1023 - r0g);
        bool a2 = (col     >= 1023 - r1g);
        bool a3 = (col + 1 >= 1023 - r1g);
        w0.x = a0 ? sa[n][0] : 0.f;
        w0.y = a1 ? sa[n][1] : 0.f;
        w1.x = a2 ? sa[n][2] : 0.f;
        w1.y = a3 ? sa[n][3] : 0.f;
        *(float2*)(outp + ((size_t)r0g << 10) + col) = w0;
        *(float2*)(outp + ((size_t)r1g << 10) + col) = w1;
        if (a0) srq[((size_t)r0g << 10) + col     - 1023 + r0g] = sa[n][0];
        if (a1) srq[((size_t)r0g << 10) + col + 1 - 1023 + r0g] = sa[n][1];
        if (a2) srq[((size_t)r1g << 10) + col     - 1023 + r1g] = sa[n][2];
        if (a3) srq[((size_t)r1g << 10) + col + 1 - 1023 + r1g] = sa[n][3];
    }
}

// zero-fill the 56 all-zero qe tiles per bh
__global__ __launch_bounds__(256) void qe_zero(float* __restrict__ qe_out)
{
    int t = blockIdx.x;              // 0..55
    int a = 0;
    while (t >= 14 - 2 * a) { t -= 14 - 2 * a; a++; }
    const int i0 = a * 128, k0 = t * 64;
    const int bh = blockIdx.y;
    float* outp = qe_out + ((size_t)bh << 20);
    const float4 z = make_float4(0.f, 0.f, 0.f, 0.f);
    for (int idx = threadIdx.x; idx < 2048; idx += 256) {
        int r = idx >> 4, k4 = (idx & 15) << 2;
        *(float4*)(outp + ((size_t)(i0 + r) << 10) + k0 + k4) = z;
    }
}

// zero S_rel strict upper triangle (j > i)
__global__ __launch_bounds__(256) void srel_zero(float* __restrict__ srel)
{
    const int i0 = blockIdx.x * 64;
    float* srp = srel + ((size_t)blockIdx.y << 20);
    const int t = threadIdx.x;
    const float4 z = make_float4(0.f, 0.f, 0.f, 0.f);
    for (int r = 0; r < 64; r++) {
        int i = i0 + r;
        float* row = srp + ((size_t)i << 10);
        int jb = i + 1;
        int ja = (jb + 3) & ~3;
        if (t < ja - jb && jb + t < 1024) row[jb + t] = 0.f;
        int j4 = ja + (t << 2);
        if (j4 < 1024) *(float4*)(row + j4) = z;
    }
}

// ============================================================
// Flash attention via HMMA, pre-split Q/K/V, cp.async KV pipeline.
// Writes O pre-split (g_Oh/g_Ol) for the final GEMM.
// ============================================================
#define AT_Q_BYTES (128 * KST * 2)      // 18432
#define AT_KV_BYTES (64 * KST * 2)      // 9216
#define AT_STAGE (4 * AT_KV_BYTES)      // 36864
#define AT_SMEM (2 * AT_Q_BYTES + 2 * AT_STAGE)   // 110592

__global__ __launch_bounds__(256, 1) void attn_hmma(const float* __restrict__ srel)
{
    extern __shared__ char smemc[];
    __nv_bfloat16* Qh = (__nv_bfloat16*)smemc;
    __nv_bfloat16* Ql = Qh + 128 * KST;
    const uint32_t sb = smem_u32(smemc);
    const uint32_t kvbase = sb + 2 * AT_Q_BYTES;

    const int tid = threadIdx.x;
    const int wid = tid >> 5;
    const int lane = tid & 31;
    const int g = lane >> 2, tg = lane & 3;
    const int a = 7 - blockIdx.x;
    const int i0 = a * 128;
    const int bh = blockIdx.y;
    const int b = bh >> 4, h = bh & 15;
    const int mo = wid * 16;
    const int njt = 2 * a + 2;
    const int bS = b * SEQ;

    const float* srp = srel + ((size_t)bh << 20);

    auto loadKV = [&](int t, int s) {
        uint32_t base = kvbase + s * AT_STAGE;
        const int j0 = t * 64;
        #pragma unroll
        for (int it = 0; it < 2; it++) {
            int idx = tid + it * 256;
            int r = idx >> 3, sg = idx & 7;
            size_t go = (size_t)(bS + j0 + r) * 1024 + h * 64 + sg * 8;
            uint32_t so = r * 144 + sg * 16;
            cp16(base + so, g_Kh + go);
            cp16(base + AT_KV_BYTES + so, g_Kl + go);
            cp16(base + 2 * AT_KV_BYTES + so, g_Vh + go);
            cp16(base + 3 * AT_KV_BYTES + so, g_Vl + go);
        }
        cp_commit();
    };

    loadKV(0, 0);

    // stage Q (pre-split, plain loads)
    #pragma unroll
    for (int it = 0; it < 4; it++) {
        int idx = tid + it * 256;
        int r = idx >> 3, sg = idx & 7;
        size_t go = (size_t)(bS + i0 + r) * 1024 + h * 64 + sg * 8;
        *(uint4*)((char*)Qh + r * 144 + sg * 16) = *(const uint4*)(g_Qh + go);
        *(uint4*)((char*)Ql + r * 144 + sg * 16) = *(const uint4*)(g_Ql + go);
    }
    __syncthreads();

    uint32_t qh[4][4], ql[4][4];
    #pragma unroll
    for (int kb = 0; kb < 4; kb++) {
        uint32_t off = ((mo + (lane & 15)) * KST + kb * 16 + (lane >> 4) * 8) * 2;
        ldmat_x4(qh[kb][0], qh[kb][1], qh[kb][2], qh[kb][3], sb + off);
        ldmat_x4(ql[kb][0], ql[kb][1], ql[kb][2], ql[kb][3], sb + AT_Q_BYTES + off);
    }

    float O[8][4];
    #pragma unroll
    for (int n = 0; n < 8; n++)
        #pragma unroll
        for (int e = 0; e < 4; e++) O[n][e] = 0.f;
    float m0 = -1e30f, m1 = -1e30f, l0 = 0.f, l1 = 0.f;

    const int r0g = i0 + mo + g;
    const int r1g = r0g + 8;

    for (int t = 0; t < njt; t++) {
        const int s = t & 1;
        const int j0 = t * 64;
        if (t + 1 < njt) { loadKV(t + 1, s ^ 1); cp_wait1(); }
        else cp_wait0();
        __syncthreads();

        if (i0 + mo + 15 >= j0) {
            const uint32_t sKh = kvbase + s * AT_STAGE;
            const uint32_t sKl = sKh + AT_KV_BYTES;
            const uint32_t sVh = sKh + 2 * AT_KV_BYTES;
            const uint32_t sVl = sKh + 3 * AT_KV_BYTES;

            float sa[8][4];
            #pragma unroll
            for (int n = 0; n < 8; n++)
                #pragma unroll
                for (int e = 0; e < 4; e++) sa[n][e] = 0.f;
            #pragma unroll
            for (int ks = 0; ks < 4; ks++) {
                uint32_t kbh[8][2], kbl[8][2];
                #pragma unroll
                for (int np = 0; np < 4; np++) {
                    uint32_t off = ((np * 16 + ((lane >> 4) << 3) + (lane & 7)) * KST
                                    + ks * 16 + ((lane >> 3) & 1) * 8) * 2;
                    uint32_t t0, t1, t2, t3;
                    ldmat_x4(t0, t1, t2, t3, sKh + off);
                    kbh[2 * np][0] = t0; kbh[2 * np][1] = t1;
                    kbh[2 * np + 1][0] = t2; kbh[2 * np + 1][1] = t3;
                    ldmat_x4(t0, t1, t2, t3, sKl + off);
                    kbl[2 * np][0] = t0; kbl[2 * np][1] = t1;
                    kbl[2 * np + 1][0] = t2; kbl[2 * np + 1][1] = t3;
                }
                #pragma unroll
                for (int n = 0; n < 8; n++) {
                    mma_bf16(sa[n], qh[ks], kbh[n][0], kbh[n][1]);
                    mma_bf16(sa[n], qh[ks], kbl[n][0], kbl[n][1]);
                    mma_bf16(sa[n], ql[ks], kbh[n][0], kbh[n][1]);
                }
            }

            float tm0 = -1e30f, tm1 = -1e30f;
            #pragma unroll
            for (int n = 0; n < 8; n++) {
                int col = j0 + n * 8 + tg * 2;
                float2 e0 = *(const float2*)(srp + ((size_t)r0g << 10) + col);
                float2 e1 = *(const float2*)(srp + ((size_t)r1g << 10) + col);
                sa[n][0] = (col     <= r0g) ? sa[n][0] * 0.125f + e0.x : -1e30f;
                sa[n][1] = (col + 1 <= r0g) ? sa[n][1] * 0.125f + e0.y : -1e30f;
                sa[n][2] = (col     <= r1g) ? sa[n][2] * 0.125f + e1.x : -1e30f;
                sa[n][3] = (col + 1 <= r1g) ? sa[n][3] * 0.125f + e1.y : -1e30f;
                tm0 = fmaxf(tm0, fmaxf(sa[n][0], sa[n][1]));
                tm1 = fmaxf(tm1, fmaxf(sa[n][2], sa[n][3]));
            }
            tm0 = fmaxf(tm0, __shfl_xor_sync(0xffffffffu, tm0, 1));
            tm0 = fmaxf(tm0, __shfl_xor_sync(0xffffffffu, tm0, 2));
            tm1 = fmaxf(tm1, __shfl_xor_sync(0xffffffffu, tm1, 1));
            tm1 = fmaxf(tm1, __shfl_xor_sync(0xffffffffu, tm1, 2));
            float nm0 = fmaxf(m0, tm0), nm1 = fmaxf(m1, tm1);
            float al0 = ex2((m0 - nm0) * L2E), al1 = ex2((m1 - nm1) * L2E);
            m0 = nm0; m1 = nm1;

            float rs0 = 0.f, rs1 = 0.f;
            #pragma unroll
            for (int n = 0; n < 8; n++) {
                sa[n][0] = ex2((sa[n][0] - nm0) * L2E);
                sa[n][1] = ex2((sa[n][1] - nm0) * L2E);
                sa[n][2] = ex2((sa[n][2] - nm1) * L2E);
                sa[n][3] = ex2((sa[n][3] - nm1) * L2E);
                rs0 += sa[n][0] + sa[n][1];
                rs1 += sa[n][2] + sa[n][3];
            }
            rs0 += __shfl_xor_sync(0xffffffffu, rs0, 1);
            rs0 += __shfl_xor_sync(0xffffffffu, rs0, 2);
            rs1 += __shfl_xor_sync(0xffffffffu, rs1, 1);
            rs1 += __shfl_xor_sync(0xffffffffu, rs1, 2);
            l0 = l0 * al0 + rs0;
            l1 = l1 * al1 + rs1;

            #pragma unroll
            for (int n = 0; n < 8; n++) {
                O[n][0] *= al0; O[n][1] *= al0;
                O[n][2] *= al1; O[n][3] *= al1;
            }

            uint32_t pa[4][4], pb[4][4];
            #pragma unroll
            for (int kb = 0; kb < 4; kb++) {
                split2(sa[2 * kb][0],     sa[2 * kb][1],     pa[kb][0], pb[kb][0]);
                split2(sa[2 * kb][2],     sa[2 * kb][3],     pa[kb][1], pb[kb][1]);
                split2(sa[2 * kb + 1][0], sa[2 * kb + 1][1], pa[kb][2], pb[kb][2]);
                split2(sa[2 * kb + 1][2], sa[2 * kb + 1][3], pa[kb][3], pb[kb][3]);
            }

            #pragma unroll
            for (int kb = 0; kb < 4; kb++) {
                uint32_t vbh[8][2], vbl[8][2];
                #pragma unroll
                for (int np = 0; np < 4; np++) {
                    uint32_t off = ((kb * 16 + (lane & 15)) * KST
                                    + np * 16 + ((lane >> 4) << 3)) * 2;
                    uint32_t t0, t1, t2, t3;
                    ldmat_x4t(t0, t1, t2, t3, sVh + off);
                    vbh[2 * np][0] = t0; vbh[2 * np][1] = t1;
                    vbh[2 * np + 1][0] = t2; vbh[2 * np + 1][1] = t3;
                    ldmat_x4t(t0, t1, t2, t3, sVl + off);
                    vbl[2 * np][0] = t0; vbl[2 * np][1] = t1;
                    vbl[2 * np + 1][0] = t2; vbl[2 * np + 1][1] = t3;
                }
                #pragma unroll
                for (int n = 0; n < 8; n++) {
                    mma_bf16(O[n], pa[kb], vbh[n][0], vbh[n][1]);
                    mma_bf16(O[n], pa[kb], vbl[n][0], vbl[n][1]);
                    mma_bf16(O[n], pb[kb], vbh[n][0], vbh[n][1]);
                }
            }
        }
        __syncthreads();
    }

    // epilogue: write O pre-split for the final GEMM
    float iv0 = 1.f / l0, iv1 = 1.f / l1;
    #pragma unroll
    for (int n = 0; n < 8; n++) {
        int col = n * 8 + tg * 2;
        size_t off0 = (size_t)(bS + r0g) * 1024 + h * 64 + col;
        size_t off1 = off0 + 8 * 1024;
        uint32_t h0, l0u, h1, l1u;
        split2(O[n][0] * iv0, O[n][1] * iv0, h0, l0u);
        split2(O[n][2] * iv1, O[n][3] * iv1, h1, l1u);
        *(uint32_t*)(g_Oh + off0) = h0;
        *(uint32_t*)(g_Ol + off0) = l0u;
        *(uint32_t*)(g_Oh + off1) = h1;
        *(uint32_t*)(g_Ol + off1) = l1u;
    }
}

// ============================================================
// Launcher
// ============================================================
extern "C" void kernel_launch(void* const* d_in, const int* in_sizes, int n_in,
                              void* d_out, int out_size)
{
    (void)in_sizes; (void)n_in; (void)out_size;
    const float* q  = (const float*)d_in[0];
    const float* k  = (const float*)d_in[1];
    const float* v  = (const float*)d_in[2];
    const float* Wq = (const float*)d_in[4];
    const float* bq = (const float*)d_in[5];
    const float* Wk = (const float*)d_in[6];
    const float* bk = (const float*)d_in[7];
    const float* Wv = (const float*)d_in[8];
    const float* bv = (const float*)d_in[9];
    const float* Wo = (const float*)d_in[10];
    const float* bo = (const float*)d_in[11];
    const float* er = (const float*)d_in[12];

    float* out  = (float*)d_out;             // (B,S,D)
    float* srel = out + OUT_ELEMS;           // (B,H,S,S)
    float* qe   = srel + SREL_ELEMS;         // (B,H,S,S)

    #define GET(sym, var) __nv_bfloat16* var; cudaGetSymbolAddress((void**)&var, sym)
    GET(g_qh, qh);  GET(g_ql, ql);
    GET(g_kh, kh);  GET(g_kl, kl);
    GET(g_vh, vh);  GET(g_vl, vl);
    GET(g_Wqh, Wqh); GET(g_Wql, Wql);
    GET(g_Wkh, Wkh); GET(g_Wkl, Wkl);
    GET(g_Wvh, Wvh); GET(g_Wvl, Wvl);
    GET(g_Woh, Woh); GET(g_Wol, Wol);
    GET(g_Qh, Qhp); GET(g_Ql, Qlp);
    GET(g_Kh, Khp); GET(g_Kl, Klp);
    GET(g_Vh, Vhp); GET(g_Vl, Vlp);
    GET(g_Oh, Ohp); GET(g_Ol, Olp);
    #undef GET

    cudaFuncSetAttribute(gemm_bf,
                         cudaFuncAttributeMaxDynamicSharedMemorySize, GB_SMEM);
    cudaFuncSetAttribute(qe_hmma,
                         cudaFuncAttributeMaxDynamicSharedMemorySize, QE_SMEM);
    cudaFuncSetAttribute(attn_hmma,
                         cudaFuncAttributeMaxDynamicSharedMemorySize, AT_SMEM);

    // one-time splits
    cvt_split<<<OUT_ELEMS / 1024, 256>>>(q, qh, ql);
    cvt_split<<<OUT_ELEMS / 1024, 256>>>(k, kh, kl);
    cvt_split<<<OUT_ELEMS / 1024, 256>>>(v, vh, vl);
    cvt_split<<<D_MODEL * D_MODEL / 1024, 256>>>(Wq, Wqh, Wql);
    cvt_split<<<D_MODEL * D_MODEL / 1024, 256>>>(Wk, Wkh, Wkl);
    cvt_split<<<D_MODEL * D_MODEL / 1024, 256>>>(Wv, Wvh, Wvl);
    cvt_split<<<D_MODEL * D_MODEL / 1024, 256>>>(Wo, Woh, Wol);

    dim3 gproj(D_MODEL / 128, ROWS / 128);   // (8, 16)

    gemm_bf<<<gproj, 256, GB_SMEM>>>(qh, ql, Wqh, Wql, bq, nullptr, Qhp, Qlp);
    gemm_bf<<<gproj, 256, GB_SMEM>>>(kh, kl, Wkh, Wkl, bk, nullptr, Khp, Klp);
    gemm_bf<<<gproj, 256, GB_SMEM>>>(vh, vl, Wvh, Wvl, bv, nullptr, Vhp, Vlp);

    qe_hmma<<<dim3(72, BATCH * NUM_HEADS), 256, QE_SMEM>>>(er, qe, srel);
    qe_zero<<<dim3(56, BATCH * NUM_HEADS), 256>>>(qe);
    srel_zero<<<dim3(16, BATCH * NUM_HEADS), 256>>>(srel);

    attn_hmma<<<dim3(8, BATCH * NUM_HEADS), 256, AT_SMEM>>>(srel);

    gemm_bf<<<gproj, 256, GB_SMEM>>>(Ohp, Olp, Woh, Wol, bo, out, nullptr, nullptr);
}

// round 12
// speedup vs baseline: 4.1220x; 1.3510x over previous
#include <cuda_runtime.h>
#include <cuda_fp16.h>
#include <math.h>
#include <stdint.h>

#define D_MODEL 1024
#define NUM_HEADS 16
#define HEAD_DIM 64
#define SEQ 1024
#define BATCH 2
#define ROWS (BATCH * SEQ)            // 2048
#define OUT_ELEMS   (ROWS * D_MODEL)  // 2,097,152
#define SREL_ELEMS  (BATCH * NUM_HEADS * SEQ * SEQ)  // 33,554,432
#define L2E 1.4426950408889634f

// ---- helpers ----
__device__ __forceinline__ uint32_t smem_u32(const void* p) {
    uint32_t a;
    asm("{ .reg .u64 t; cvta.to.shared.u64 t, %1; cvt.u32.u64 %0, t; }"
        : "=r"(a) : "l"(p));
    return a;
}
__device__ __forceinline__ void cp16(uint32_t dst, const void* src) {
    asm volatile("cp.async.cg.shared.global [%0], [%1], 16;" :: "r"(dst), "l"(src));
}
__device__ __forceinline__ void cp_commit() {
    asm volatile("cp.async.commit_group;" ::: "memory");
}
__device__ __forceinline__ void cp_wait0() {
    asm volatile("cp.async.wait_group 0;" ::: "memory");
}
__device__ __forceinline__ void cp_wait1() {
    asm volatile("cp.async.wait_group 1;" ::: "memory");
}
__device__ __forceinline__ void ldmat_x4(uint32_t& r0, uint32_t& r1,
                                         uint32_t& r2, uint32_t& r3, uint32_t addr) {
    asm volatile("ldmatrix.sync.aligned.m8n8.x4.shared.b16 {%0,%1,%2,%3}, [%4];"
                 : "=r"(r0), "=r"(r1), "=r"(r2), "=r"(r3) : "r"(addr));
}
__device__ __forceinline__ void ldmat_x4t(uint32_t& r0, uint32_t& r1,
                                          uint32_t& r2, uint32_t& r3, uint32_t addr) {
    asm volatile("ldmatrix.sync.aligned.m8n8.x4.trans.shared.b16 {%0,%1,%2,%3}, [%4];"
                 : "=r"(r0), "=r"(r1), "=r"(r2), "=r"(r3) : "r"(addr));
}
__device__ __forceinline__ void ldmat_x2t(uint32_t& r0, uint32_t& r1, uint32_t addr) {
    asm volatile("ldmatrix.sync.aligned.m8n8.x2.trans.shared.b16 {%0,%1}, [%2];"
                 : "=r"(r0), "=r"(r1) : "r"(addr));
}
__device__ __forceinline__ void mma_f16(float* c, const uint32_t* a,
                                        uint32_t b0, uint32_t b1) {
    asm volatile(
        "mma.sync.aligned.m16n8k16.row.col.f32.f16.f16.f32 "
        "{%0,%1,%2,%3}, {%4,%5,%6,%7}, {%8,%9}, {%0,%1,%2,%3};"
        : "+f"(c[0]), "+f"(c[1]), "+f"(c[2]), "+f"(c[3])
        : "r"(a[0]), "r"(a[1]), "r"(a[2]), "r"(a[3]), "r"(b0), "r"(b1));
}
__device__ __forceinline__ float ex2(float x) {
    float r; asm("ex2.approx.f32 %0,%1;" : "=f"(r) : "f"(x)); return r;
}
__device__ __forceinline__ uint32_t packh2(float x, float y) {
    __half2 h = __floats2half2_rn(x, y);
    return *(uint32_t*)&h;
}
// fp16 2-way split: x = hi + lo (to ~2^-22)
__device__ __forceinline__ void split2h(float x, float y, uint32_t& hi, uint32_t& lo) {
    __half hx = __float2half_rn(x), hy = __float2half_rn(y);
    __half lx = __float2half_rn(x - __half2float(hx));
    __half ly = __float2half_rn(y - __half2float(hy));
    __half2 h; h.x = hx; h.y = hy;
    __half2 l; l.x = lx; l.y = ly;
    hi = *(uint32_t*)&h;
    lo = *(uint32_t*)&l;
}

// -------- persistent scratch (fp16) --------
__device__ __half g_qh[OUT_ELEMS], g_ql[OUT_ELEMS];          // input q split
__device__ __half g_kh[OUT_ELEMS], g_vh[OUT_ELEMS];          // inputs k,v hi
__device__ __half g_Wqh[D_MODEL * D_MODEL], g_Wql[D_MODEL * D_MODEL];
__device__ __half g_Wkh[D_MODEL * D_MODEL];
__device__ __half g_Wvh[D_MODEL * D_MODEL];
__device__ __half g_Woh[D_MODEL * D_MODEL];
__device__ __half g_Qh[OUT_ELEMS], g_Ql[OUT_ELEMS];          // Q proj split
__device__ __half g_Kh[OUT_ELEMS];                           // K proj hi
__device__ __half g_Vh[OUT_ELEMS];                           // V proj hi
__device__ __half g_Oh[OUT_ELEMS];                           // attn out hi

// ============================================================
// f32 -> fp16 converters
// ============================================================
__global__ __launch_bounds__(256) void cvt_split(
    const float* __restrict__ s, __half* __restrict__ hi, __half* __restrict__ lo)
{
    int i = blockIdx.x * 256 + threadIdx.x;
    float4 v = ((const float4*)s)[i];
    uint32_t h01, l01, h23, l23;
    split2h(v.x, v.y, h01, l01);
    split2h(v.z, v.w, h23, l23);
    ((uint2*)hi)[i] = make_uint2(h01, h23);
    ((uint2*)lo)[i] = make_uint2(l01, l23);
}
__global__ __launch_bounds__(256) void cvt_hi(
    const float* __restrict__ s, __half* __restrict__ hi)
{
    int i = blockIdx.x * 256 + threadIdx.x;
    float4 v = ((const float4*)s)[i];
    ((uint2*)hi)[i] = make_uint2(packh2(v.x, v.y), packh2(v.z, v.w));
}

#define AST 72
#define BST 136
#define GB_A_BYTES (128 * AST * 2)      // 18432
#define GB_B_BYTES (64 * BST * 2)       // 17408

// ============================================================
// 3-pass split GEMM (Q projection): C = A@B + bias, split fp16 out.
// ============================================================
#define G3_STAGE (2 * GB_A_BYTES + 2 * GB_B_BYTES)   // 71680
#define G3_SMEM (2 * G3_STAGE)                       // 143360

__global__ __launch_bounds__(256, 1) void gemm3(
    const __half* __restrict__ Ahg, const __half* __restrict__ Alg,
    const __half* __restrict__ Bhg, const __half* __restrict__ Blg,
    const float* __restrict__ bias,
    __half* __restrict__ Ch, __half* __restrict__ Cl)
{
    extern __shared__ char smemc[];
    const uint32_t sb = smem_u32(smemc);
    const int tid = threadIdx.x;
    const int wid = tid >> 5;
    const int lane = tid & 31;
    const int row0 = blockIdx.y * 128;
    const int col0 = blockIdx.x * 128;
    const int mo = (wid >> 1) * 32;
    const int no = (wid & 1) * 64;

    float acc[2][8][4];
    #pragma unroll
    for (int mi = 0; mi < 2; mi++)
        #pragma unroll
        for (int ni = 0; ni < 8; ni++)
            #pragma unroll
            for (int e = 0; e < 4; e++) acc[mi][ni][e] = 0.f;

    auto load_chunk = [&](int c, int s) {
        uint32_t base = sb + s * G3_STAGE;
        const int k0 = c * 64;
        #pragma unroll
        for (int it = 0; it < 4; it++) {
            int idx = tid + it * 256;
            int r = idx >> 3, sg = idx & 7;
            size_t go = (size_t)(row0 + r) * 1024 + k0 + sg * 8;
            uint32_t so = r * 144 + sg * 16;
            cp16(base + so, Ahg + go);
            cp16(base + GB_A_BYTES + so, Alg + go);
        }
        #pragma unroll
        for (int it = 0; it < 4; it++) {
            int idx = tid + it * 256;
            int r = idx >> 4, sg = idx & 15;
            size_t go = (size_t)(k0 + r) * 1024 + col0 + sg * 8;
            uint32_t so = r * 272 + sg * 16;
            cp16(base + 2 * GB_A_BYTES + so, Bhg + go);
            cp16(base + 2 * GB_A_BYTES + GB_B_BYTES + so, Blg + go);
        }
        cp_commit();
    };

    load_chunk(0, 0);

    for (int c = 0; c < 16; c++) {
        const int s = c & 1;
        if (c + 1 < 16) { load_chunk(c + 1, s ^ 1); cp_wait1(); }
        else cp_wait0();
        __syncthreads();

        const uint32_t sAh = sb + s * G3_STAGE;
        const uint32_t sAl = sAh + GB_A_BYTES;
        const uint32_t sBh = sAh + 2 * GB_A_BYTES;
        const uint32_t sBl = sBh + GB_B_BYTES;

        #pragma unroll
        for (int ks = 0; ks < 4; ks++) {
            uint32_t ah[2][4], al[2][4];
            #pragma unroll
            for (int mi = 0; mi < 2; mi++) {
                uint32_t off = ((mo + mi * 16 + (lane & 15)) * AST
                                + ks * 16 + (lane >> 4) * 8) * 2;
                ldmat_x4(ah[mi][0], ah[mi][1], ah[mi][2], ah[mi][3], sAh + off);
                ldmat_x4(al[mi][0], al[mi][1], al[mi][2], al[mi][3], sAl + off);
            }
            #pragma unroll
            for (int ni = 0; ni < 8; ni++) {
                uint32_t offB = ((ks * 16 + (lane & 15)) * BST + no + ni * 8) * 2;
                uint32_t bh0, bh1, bl0, bl1;
                ldmat_x2t(bh0, bh1, sBh + offB);
                ldmat_x2t(bl0, bl1, sBl + offB);
                #pragma unroll
                for (int mi = 0; mi < 2; mi++) {
                    mma_f16(acc[mi][ni], ah[mi], bh0, bh1);
                    mma_f16(acc[mi][ni], ah[mi], bl0, bl1);
                    mma_f16(acc[mi][ni], al[mi], bh0, bh1);
                }
            }
        }
        __syncthreads();
    }

    const int g = lane >> 2, tg = lane & 3;
    #pragma unroll
    for (int mi = 0; mi < 2; mi++) {
        #pragma unroll
        for (int ni = 0; ni < 8; ni++) {
            int colb = col0 + no + ni * 8 + tg * 2;
            float2 bb = *(const float2*)(bias + colb);
            int r0 = row0 + mo + mi * 16 + g;
            uint32_t h0, l0, h1, l1;
            split2h(acc[mi][ni][0] + bb.x, acc[mi][ni][1] + bb.y, h0, l0);
            split2h(acc[mi][ni][2] + bb.x, acc[mi][ni][3] + bb.y, h1, l1);
            *(uint32_t*)(Ch + (size_t)r0 * 1024 + colb) = h0;
            *(uint32_t*)(Cl + (size_t)r0 * 1024 + colb) = l0;
            *(uint32_t*)(Ch + (size_t)(r0 + 8) * 1024 + colb) = h1;
            *(uint32_t*)(Cl + (size_t)(r0 + 8) * 1024 + colb) = l1;
        }
    }
}

// ============================================================
// 1-pass fp16 GEMM (K/V/O projections): C = A@B + bias.
// Output: f32 (Cf) or fp16 (Ch).
// ============================================================
#define G1_STAGE (GB_A_BYTES + GB_B_BYTES)   // 35840
#define G1_SMEM (2 * G1_STAGE)               // 71680

__global__ __launch_bounds__(256, 1) void gemm1(
    const __half* __restrict__ Ahg, const __half* __restrict__ Bhg,
    const float* __restrict__ bias, float* __restrict__ Cf,
    __half* __restrict__ Ch)
{
    extern __shared__ char smemc[];
    const uint32_t sb = smem_u32(smemc);
    const int tid = threadIdx.x;
    const int wid = tid >> 5;
    const int lane = tid & 31;
    const int row0 = blockIdx.y * 128;
    const int col0 = blockIdx.x * 128;
    const int mo = (wid >> 1) * 32;
    const int no = (wid & 1) * 64;

    float acc[2][8][4];
    #pragma unroll
    for (int mi = 0; mi < 2; mi++)
        #pragma unroll
        for (int ni = 0; ni < 8; ni++)
            #pragma unroll
            for (int e = 0; e < 4; e++) acc[mi][ni][e] = 0.f;

    auto load_chunk = [&](int c, int s) {
        uint32_t base = sb + s * G1_STAGE;
        const int k0 = c * 64;
        #pragma unroll
        for (int it = 0; it < 4; it++) {
            int idx = tid + it * 256;
            int r = idx >> 3, sg = idx & 7;
            cp16(base + r * 144 + sg * 16,
                 Ahg + (size_t)(row0 + r) * 1024 + k0 + sg * 8);
        }
        #pragma unroll
        for (int it = 0; it < 4; it++) {
            int idx = tid + it * 256;
            int r = idx >> 4, sg = idx & 15;
            cp16(base + GB_A_BYTES + r * 272 + sg * 16,
                 Bhg + (size_t)(k0 + r) * 1024 + col0 + sg * 8);
        }
        cp_commit();
    };

    load_chunk(0, 0);

    for (int c = 0; c < 16; c++) {
        const int s = c & 1;
        if (c + 1 < 16) { load_chunk(c + 1, s ^ 1); cp_wait1(); }
        else cp_wait0();
        __syncthreads();

        const uint32_t sAh = sb + s * G1_STAGE;
        const uint32_t sBh = sAh + GB_A_BYTES;

        #pragma unroll
        for (int ks = 0; ks < 4; ks++) {
            uint32_t ah[2][4];
            #pragma unroll
            for (int mi = 0; mi < 2; mi++) {
                uint32_t off = ((mo + mi * 16 + (lane & 15)) * AST
                                + ks * 16 + (lane >> 4) * 8) * 2;
                ldmat_x4(ah[mi][0], ah[mi][1], ah[mi][2], ah[mi][3], sAh + off);
            }
            #pragma unroll
            for (int ni = 0; ni < 8; ni++) {
                uint32_t offB = ((ks * 16 + (lane & 15)) * BST + no + ni * 8) * 2;
                uint32_t bh0, bh1;
                ldmat_x2t(bh0, bh1, sBh + offB);
                #pragma unroll
                for (int mi = 0; mi < 2; mi++)
                    mma_f16(acc[mi][ni], ah[mi], bh0, bh1);
            }
        }
        __syncthreads();
    }

    const int g = lane >> 2, tg = lane & 3;
    #pragma unroll
    for (int mi = 0; mi < 2; mi++) {
        #pragma unroll
        for (int ni = 0; ni < 8; ni++) {
            int colb = col0 + no + ni * 8 + tg * 2;
            float2 bb = *(const float2*)(bias + colb);
            int r0 = row0 + mo + mi * 16 + g;
            float w0x = acc[mi][ni][0] + bb.x, w0y = acc[mi][ni][1] + bb.y;
            float w1x = acc[mi][ni][2] + bb.x, w1y = acc[mi][ni][3] + bb.y;
            if (Cf) {
                *(float2*)(Cf + (size_t)r0 * 1024 + colb) = make_float2(w0x, w0y);
                *(float2*)(Cf + (size_t)(r0 + 8) * 1024 + colb) = make_float2(w1x, w1y);
            } else {
                *(uint32_t*)(Ch + (size_t)r0 * 1024 + colb) = packh2(w0x, w0y);
                *(uint32_t*)(Ch + (size_t)(r0 + 8) * 1024 + colb) = packh2(w1x, w1y);
            }
        }
    }
}

// ============================================================
// qe via HMMA (3-pass fp16 split), fused S_rel stores.
// ============================================================
#define KST 72
#define QE_SMEM ((2 * 128 * KST + 2 * 64 * KST) * 2)   // 55296 B

__global__ __launch_bounds__(256, 1) void qe_hmma(
    const float* __restrict__ er, float* __restrict__ qe_out,
    float* __restrict__ srel_out)
{
    extern __shared__ __half sh[];
    __half* Qh = sh;
    __half* Ql = Qh + 128 * KST;
    __half* Eh = Ql + 128 * KST;
    __half* El = Eh + 64 * KST;

    int t = blockIdx.x;              // 0..71
    int a = 0;
    while (t >= 2 * a + 2) { t -= 2 * a + 2; a++; }
    const int c = 14 - 2 * a + t;
    const int i0 = a * 128, k0 = c * 64;
    const int bh = blockIdx.y;
    const int b = bh >> 4, h = bh & 15;
    const int tid = threadIdx.x;
    const int wid = tid >> 5;
    const int lane = tid & 31;
    const int g = lane >> 2, tg = lane & 3;
    const int mo = wid * 16;
    const int bS = b * SEQ;

    #pragma unroll
    for (int it = 0; it < 4; it++) {
        int idx = tid + it * 256;
        int r = idx >> 3, sg = idx & 7;
        size_t go = (size_t)(bS + i0 + r) * 1024 + h * 64 + sg * 8;
        *(uint4*)((char*)Qh + r * 144 + sg * 16) = *(const uint4*)(g_Qh + go);
        *(uint4*)((char*)Ql + r * 144 + sg * 16) = *(const uint4*)(g_Ql + go);
    }
    #pragma unroll
    for (int it = 0; it < 4; it++) {
        int idx = tid + it * 256;
        int r = idx >> 4, c4 = (idx & 15) << 2;
        float4 v = *(const float4*)(er + (size_t)(k0 + r) * HEAD_DIM + c4);
        uint32_t h01, l01, h23, l23;
        split2h(v.x, v.y, h01, l01);
        split2h(v.z, v.w, h23, l23);
        *(uint2*)(Eh + r * KST + c4) = make_uint2(h01, h23);
        *(uint2*)(El + r * KST + c4) = make_uint2(l01, l23);
    }
    __syncthreads();

    const uint32_t sQh = smem_u32(Qh), sQl = smem_u32(Ql);
    const uint32_t sEh = smem_u32(Eh), sEl = smem_u32(El);

    uint32_t qh[4][4], ql[4][4];
    #pragma unroll
    for (int kb = 0; kb < 4; kb++) {
        uint32_t off = ((mo + (lane & 15)) * KST + kb * 16 + (lane >> 4) * 8) * 2;
        ldmat_x4(qh[kb][0], qh[kb][1], qh[kb][2], qh[kb][3], sQh + off);
        ldmat_x4(ql[kb][0], ql[kb][1], ql[kb][2], ql[kb][3], sQl + off);
    }

    float sa[8][4];
    #pragma unroll
    for (int n = 0; n < 8; n++)
        #pragma unroll
        for (int e = 0; e < 4; e++) sa[n][e] = 0.f;

    #pragma unroll
    for (int ks = 0; ks < 4; ks++) {
        uint32_t ebh[8][2], ebl[8][2];
        #pragma unroll
        for (int np = 0; np < 4; np++) {
            uint32_t off = ((np * 16 + ((lane >> 4) << 3) + (lane & 7)) * KST
                            + ks * 16 + ((lane >> 3) & 1) * 8) * 2;
            uint32_t t0, t1, t2, t3;
            ldmat_x4(t0, t1, t2, t3, sEh + off);
            ebh[2 * np][0] = t0; ebh[2 * np][1] = t1;
            ebh[2 * np + 1][0] = t2; ebh[2 * np + 1][1] = t3;
            ldmat_x4(t0, t1, t2, t3, sEl + off);
            ebl[2 * np][0] = t0; ebl[2 * np][1] = t1;
            ebl[2 * np + 1][0] = t2; ebl[2 * np + 1][1] = t3;
        }
        #pragma unroll
        for (int n = 0; n < 8; n++) {
            mma_f16(sa[n], qh[ks], ebh[n][0], ebh[n][1]);
            mma_f16(sa[n], qh[ks], ebl[n][0], ebl[n][1]);
            mma_f16(sa[n], ql[ks], ebh[n][0], ebh[n][1]);
        }
    }

    const int r0g = i0 + mo + g;
    const int r1g = r0g + 8;
    float* outp = qe_out + ((size_t)bh << 20);
    float* srq = srel_out + ((size_t)bh << 20);
    #pragma unroll
    for (int n = 0; n < 8; n++) {
        int col = k0 + n * 8 + tg * 2;
        float2 w0, w1;
        bool a0 = (col     >= 1023 - r0g);
        bool a1 = (col + 1 >= 1023 - r0g);
        bool a2 = (col     >= 1023 - r1g);
        bool a3 = (col + 1 >= 1023 - r1g);
        w0.x = a0 ? sa[n][0] : 0.f;
        w0.y = a1 ? sa[n][1] : 0.f;
        w1.x = a2 ? sa[n][2] : 0.f;
        w1.y = a3 ? sa[n][3] : 0.f;
        *(float2*)(outp + ((size_t)r0g << 10) + col) = w0;
        *(float2*)(outp + ((size_t)r1g << 10) + col) = w1;
        if (a0) srq[((size_t)r0g << 10) + col     - 1023 + r0g] = sa[n][0];
        if (a1) srq[((size_t)r0g << 10) + col + 1 - 1023 + r0g] = sa[n][1];
        if (a2) srq[((size_t)r1g << 10) + col     - 1023 + r1g] = sa[n][2];
        if (a3) srq[((size_t)r1g << 10) + col + 1 - 1023 + r1g] = sa[n][3];
    }
}

// zero-fill the 56 all-zero qe tiles per bh
__global__ __launch_bounds__(256) void qe_zero(float* __restrict__ qe_out)
{
    int t = blockIdx.x;              // 0..55
    int a = 0;
    while (t >= 14 - 2 * a) { t -= 14 - 2 * a; a++; }
    const int i0 = a * 128, k0 = t * 64;
    const int bh = blockIdx.y;
    float* outp = qe_out + ((size_t)bh << 20);
    const float4 z = make_float4(0.f, 0.f, 0.f, 0.f);
    for (int idx = threadIdx.x; idx < 2048; idx += 256) {
        int r = idx >> 4, k4 = (idx & 15) << 2;
        *(float4*)(outp + ((size_t)(i0 + r) << 10) + k0 + k4) = z;
    }
}

// zero S_rel strict upper triangle (j > i)
__global__ __launch_bounds__(256) void srel_zero(float* __restrict__ srel)
{
    const int i0 = blockIdx.x * 64;
    float* srp = srel + ((size_t)blockIdx.y << 20);
    const int t = threadIdx.x;
    const float4 z = make_float4(0.f, 0.f, 0.f, 0.f);
    for (int r = 0; r < 64; r++) {
        int i = i0 + r;
        float* row = srp + ((size_t)i << 10);
        int jb = i + 1;
        int ja = (jb + 3) & ~3;
        if (t < ja - jb && jb + t < 1024) row[jb + t] = 0.f;
        int j4 = ja + (t << 2);
        if (j4 < 1024) *(float4*)(row + j4) = z;
    }
}

// ============================================================
// Flash attention via HMMA, 1-pass fp16, cp.async KV pipeline.
// ============================================================
#define AT_Q_BYTES (128 * KST * 2)      // 18432
#define AT_KV_BYTES (64 * KST * 2)      // 9216
#define AT_STAGE (2 * AT_KV_BYTES)      // 18432
#define AT_SMEM (AT_Q_BYTES + 2 * AT_STAGE)   // 55296

__global__ __launch_bounds__(256, 1) void attn_hmma(const float* __restrict__ srel)
{
    extern __shared__ char smemc[];
    __half* Qh = (__half*)smemc;
    const uint32_t sb = smem_u32(smemc);
    const uint32_t kvbase = sb + AT_Q_BYTES;

    const int tid = threadIdx.x;
    const int wid = tid >> 5;
    const int lane = tid & 31;
    const int g = lane >> 2, tg = lane & 3;
    const int a = 7 - blockIdx.x;
    const int i0 = a * 128;
    const int bh = blockIdx.y;
    const int b = bh >> 4, h = bh & 15;
    const int mo = wid * 16;
    const int njt = 2 * a + 2;
    const int bS = b * SEQ;

    const float* srp = srel + ((size_t)bh << 20);

    auto loadKV = [&](int t, int s) {
        uint32_t base = kvbase + s * AT_STAGE;
        const int j0 = t * 64;
        #pragma unroll
        for (int it = 0; it < 2; it++) {
            int idx = tid + it * 256;
            int r = idx >> 3, sg = idx & 7;
            size_t go = (size_t)(bS + j0 + r) * 1024 + h * 64 + sg * 8;
            uint32_t so = r * 144 + sg * 16;
            cp16(base + so, g_Kh + go);
            cp16(base + AT_KV_BYTES + so, g_Vh + go);
        }
        cp_commit();
    };

    loadKV(0, 0);

    #pragma unroll
    for (int it = 0; it < 4; it++) {
        int idx = tid + it * 256;
        int r = idx >> 3, sg = idx & 7;
        size_t go = (size_t)(bS + i0 + r) * 1024 + h * 64 + sg * 8;
        *(uint4*)((char*)Qh + r * 144 + sg * 16) = *(const uint4*)(g_Qh + go);
    }
    __syncthreads();

    uint32_t qh[4][4];
    #pragma unroll
    for (int kb = 0; kb < 4; kb++) {
        uint32_t off = ((mo + (lane & 15)) * KST + kb * 16 + (lane >> 4) * 8) * 2;
        ldmat_x4(qh[kb][0], qh[kb][1], qh[kb][2], qh[kb][3], sb + off);
    }

    float O[8][4];
    #pragma unroll
    for (int n = 0; n < 8; n++)
        #pragma unroll
        for (int e = 0; e < 4; e++) O[n][e] = 0.f;
    float m0 = -1e30f, m1 = -1e30f, l0 = 0.f, l1 = 0.f;

    const int r0g = i0 + mo + g;
    const int r1g = r0g + 8;

    for (int t = 0; t < njt; t++) {
        const int s = t & 1;
        const int j0 = t * 64;
        if (t + 1 < njt) { loadKV(t + 1, s ^ 1); cp_wait1(); }
        else cp_wait0();
        __syncthreads();

        if (i0 + mo + 15 >= j0) {
            const uint32_t sKh = kvbase + s * AT_STAGE;
            const uint32_t sVh = sKh + AT_KV_BYTES;

            float sa[8][4];
            #pragma unroll
            for (int n = 0; n < 8; n++)
                #pragma unroll
                for (int e = 0; e < 4; e++) sa[n][e] = 0.f;
            #pragma unroll
            for (int ks = 0; ks < 4; ks++) {
                uint32_t kbh[8][2];
                #pragma unroll
                for (int np = 0; np < 4; np++) {
                    uint32_t off = ((np * 16 + ((lane >> 4) << 3) + (lane & 7)) * KST
                                    + ks * 16 + ((lane >> 3) & 1) * 8) * 2;
                    uint32_t t0, t1, t2, t3;
                    ldmat_x4(t0, t1, t2, t3, sKh + off);
                    kbh[2 * np][0] = t0; kbh[2 * np][1] = t1;
                    kbh[2 * np + 1][0] = t2; kbh[2 * np + 1][1] = t3;
                }
                #pragma unroll
                for (int n = 0; n < 8; n++)
                    mma_f16(sa[n], qh[ks], kbh[n][0], kbh[n][1]);
            }

            float tm0 = -1e30f, tm1 = -1e30f;
            #pragma unroll
            for (int n = 0; n < 8; n++) {
                int col = j0 + n * 8 + tg * 2;
                float2 e0 = *(const float2*)(srp + ((size_t)r0g << 10) + col);
                float2 e1 = *(const float2*)(srp + ((size_t)r1g << 10) + col);
                sa[n][0] = (col     <= r0g) ? sa[n][0] * 0.125f + e0.x : -1e30f;
                sa[n][1] = (col + 1 <= r0g) ? sa[n][1] * 0.125f + e0.y : -1e30f;
                sa[n][2] = (col     <= r1g) ? sa[n][2] * 0.125f + e1.x : -1e30f;
                sa[n][3] = (col + 1 <= r1g) ? sa[n][3] * 0.125f + e1.y : -1e30f;
                tm0 = fmaxf(tm0, fmaxf(sa[n][0], sa[n][1]));
                tm1 = fmaxf(tm1, fmaxf(sa[n][2], sa[n][3]));
            }
            tm0 = fmaxf(tm0, __shfl_xor_sync(0xffffffffu, tm0, 1));
            tm0 = fmaxf(tm0, __shfl_xor_sync(0xffffffffu, tm0, 2));
            tm1 = fmaxf(tm1, __shfl_xor_sync(0xffffffffu, tm1, 1));
            tm1 = fmaxf(tm1, __shfl_xor_sync(0xffffffffu, tm1, 2));
            float nm0 = fmaxf(m0, tm0), nm1 = fmaxf(m1, tm1);
            float al0 = ex2((m0 - nm0) * L2E), al1 = ex2((m1 - nm1) * L2E);
            m0 = nm0; m1 = nm1;

            float rs0 = 0.f, rs1 = 0.f;
            #pragma unroll
            for (int n = 0; n < 8; n++) {
                sa[n][0] = ex2((sa[n][0] - nm0) * L2E);
                sa[n][1] = ex2((sa[n][1] - nm0) * L2E);
                sa[n][2] = ex2((sa[n][2] - nm1) * L2E);
                sa[n][3] = ex2((sa[n][3] - nm1) * L2E);
                rs0 += sa[n][0] + sa[n][1];
                rs1 += sa[n][2] + sa[n][3];
            }
            rs0 += __shfl_xor_sync(0xffffffffu, rs0, 1);
            rs0 += __shfl_xor_sync(0xffffffffu, rs0, 2);
            rs1 += __shfl_xor_sync(0xffffffffu, rs1, 1);
            rs1 += __shfl_xor_sync(0xffffffffu, rs1, 2);
            l0 = l0 * al0 + rs0;
            l1 = l1 * al1 + rs1;

            #pragma unroll
            for (int n = 0; n < 8; n++) {
                O[n][0] *= al0; O[n][1] *= al0;
                O[n][2] *= al1; O[n][3] *= al1;
            }

            // pack P fp16 single
            uint32_t pa[4][4];
            #pragma unroll
            for (int kb = 0; kb < 4; kb++) {
                pa[kb][0] = packh2(sa[2 * kb][0],     sa[2 * kb][1]);
                pa[kb][1] = packh2(sa[2 * kb][2],     sa[2 * kb][3]);
                pa[kb][2] = packh2(sa[2 * kb + 1][0], sa[2 * kb + 1][1]);
                pa[kb][3] = packh2(sa[2 * kb + 1][2], sa[2 * kb + 1][3]);
            }

            #pragma unroll
            for (int kb = 0; kb < 4; kb++) {
                uint32_t vbh[8][2];
                #pragma unroll
                for (int np = 0; np < 4; np++) {
                    uint32_t off = ((kb * 16 + (lane & 15)) * KST
                                    + np * 16 + ((lane >> 4) << 3)) * 2;
                    uint32_t t0, t1, t2, t3;
                    ldmat_x4t(t0, t1, t2, t3, sVh + off);
                    vbh[2 * np][0] = t0; vbh[2 * np][1] = t1;
                    vbh[2 * np + 1][0] = t2; vbh[2 * np + 1][1] = t3;
                }
                #pragma unroll
                for (int n = 0; n < 8; n++)
                    mma_f16(O[n], pa[kb], vbh[n][0], vbh[n][1]);
            }
        }
        __syncthreads();
    }

    float iv0 = 1.f / l0, iv1 = 1.f / l1;
    #pragma unroll
    for (int n = 0; n < 8; n++) {
        int col = n * 8 + tg * 2;
        size_t off0 = (size_t)(bS + r0g) * 1024 + h * 64 + col;
        size_t off1 = off0 + 8 * 1024;
        *(uint32_t*)(g_Oh + off0) = packh2(O[n][0] * iv0, O[n][1] * iv0);
        *(uint32_t*)(g_Oh + off1) = packh2(O[n][2] * iv1, O[n][3] * iv1);
    }
}

// ============================================================
// Launcher
// ============================================================
extern "C" void kernel_launch(void* const* d_in, const int* in_sizes, int n_in,
                              void* d_out, int out_size)
{
    (void)in_sizes; (void)n_in; (void)out_size;
    const float* q  = (const float*)d_in[0];
    const float* k  = (const float*)d_in[1];
    const float* v  = (const float*)d_in[2];
    const float* Wq = (const float*)d_in[4];
    const float* bq = (const float*)d_in[5];
    const float* Wk = (const float*)d_in[6];
    const float* bk = (const float*)d_in[7];
    const float* Wv = (const float*)d_in[8];
    const float* bv = (const float*)d_in[9];
    const float* Wo = (const float*)d_in[10];
    const float* bo = (const float*)d_in[11];
    const float* er = (const float*)d_in[12];

    float* out  = (float*)d_out;             // (B,S,D)
    float* srel = out + OUT_ELEMS;           // (B,H,S,S)
    float* qe   = srel + SREL_ELEMS;         // (B,H,S,S)

    #define GET(sym, var) __half* var; cudaGetSymbolAddress((void**)&var, sym)
    GET(g_qh, qh);  GET(g_ql, ql);
    GET(g_kh, kh);  GET(g_vh, vh);
    GET(g_Wqh, Wqh); GET(g_Wql, Wql);
    GET(g_Wkh, Wkh); GET(g_Wvh, Wvh); GET(g_Woh, Woh);
    GET(g_Qh, Qhp); GET(g_Ql, Qlp);
    GET(g_Kh, Khp); GET(g_Vh, Vhp); GET(g_Oh, Ohp);
    #undef GET

    cudaFuncSetAttribute(gemm3,
                         cudaFuncAttributeMaxDynamicSharedMemorySize, G3_SMEM);
    cudaFuncSetAttribute(gemm1,
                         cudaFuncAttributeMaxDynamicSharedMemorySize, G1_SMEM);
    cudaFuncSetAttribute(qe_hmma,
                         cudaFuncAttributeMaxDynamicSharedMemorySize, QE_SMEM);
    cudaFuncSetAttribute(attn_hmma,
                         cudaFuncAttributeMaxDynamicSharedMemorySize, AT_SMEM);

    // one-time converts
    cvt_split<<<OUT_ELEMS / 1024, 256>>>(q, qh, ql);
    cvt_hi<<<OUT_ELEMS / 1024, 256>>>(k, kh);
    cvt_hi<<<OUT_ELEMS / 1024, 256>>>(v, vh);
    cvt_split<<<D_MODEL * D_MODEL / 1024, 256>>>(Wq, Wqh, Wql);
    cvt_hi<<<D_MODEL * D_MODEL / 1024, 256>>>(Wk, Wkh);
    cvt_hi<<<D_MODEL * D_MODEL / 1024, 256>>>(Wv, Wvh);
    cvt_hi<<<D_MODEL * D_MODEL / 1024, 256>>>(Wo, Woh);

    dim3 gproj(D_MODEL / 128, ROWS / 128);   // (8, 16)

    gemm3<<<gproj, 256, G3_SMEM>>>(qh, ql, Wqh, Wql, bq, Qhp, Qlp);
    gemm1<<<gproj, 256, G1_SMEM>>>(kh, Wkh, bk, nullptr, Khp);
    gemm1<<<gproj, 256, G1_SMEM>>>(vh, Wvh, bv, nullptr, Vhp);

    qe_hmma<<<dim3(72, BATCH * NUM_HEADS), 256, QE_SMEM>>>(er, qe, srel);
    qe_zero<<<dim3(56, BATCH * NUM_HEADS), 256>>>(qe);
    srel_zero<<<dim3(16, BATCH * NUM_HEADS), 256>>>(srel);

    attn_hmma<<<dim3(8, BATCH * NUM_HEADS), 256, AT_SMEM>>>(srel);

    gemm1<<<gproj, 256, G1_SMEM>>>(Ohp, Woh, bo, out, nullptr);
}